// round 7
// baseline (speedup 1.0000x reference)
#include <cuda_runtime.h>
#include <cuda_bf16.h>
#include <cstdint>
#include <cstddef>

#define DEV __device__ __forceinline__

namespace {
constexpr int Bb = 8, F = 8192, NL = 64, D = 1024, INNER = 512, H = 8, DH = 64;
constexpr int FN = F + NL;                 // 8256
constexpr int ROWS_X = Bb * F;             // 65536
constexpr int ROWS_L = Bb * NL;            // 512
constexpr int ROWS_KV = Bb * FN;           // 66048
constexpr float LN_EPS = 1e-5f;
constexpr float QSCALE = 0.125f;           // 64^-0.5
constexpr int SPLITS = 8;
constexpr int SPLEN = FN / SPLITS;         // 1032
// gemm_kv smem pitches (bank-conflict-free fragment access)
constexpr int APITCH = 36;                 // lane bank = 4g+tg : permutation of 0..31
constexpr int BPITCH = 136;                // lane bank = 8tg+g : permutation of 0..31
constexpr int ASZ = 128 * APITCH;          // 4608 u32 per stage
constexpr int BSZ = 32 * BPITCH;           // 4352 u32 per stage
constexpr int GEMM_SMEM = (2 * ASZ + 2 * BSZ) * 4;   // 71680 B
}

// ------------------- device scratch (static: no allocations allowed) -------------------
__device__ float g_mu[ROWS_X];
__device__ float g_rstd[ROWS_X];
__device__ float g_latln[ROWS_L * D];
__device__ float g_bcat[D * 1024];                // gamma-folded [Wk | Wv]
__device__ float g_partc[64 * 1024];              // partial colsums per d-tile
__device__ float g_partb[64 * 1024];
__device__ float g_csum[1024];                    // colsum(gamma*W)
__device__ float g_bsum[1024];                    // colsum(beta*W)
__device__ float g_q[ROWS_L * INNER];
__device__ float g_k[(size_t)ROWS_KV * INNER];
__device__ float g_v[(size_t)ROWS_KV * INNER];
__device__ float g_y[ROWS_L * INNER];
__device__ float g_pm[Bb * H * SPLITS * NL];
__device__ float g_pl[Bb * H * SPLITS * NL];
__device__ float g_po[(size_t)Bb * H * SPLITS * NL * DH];

// ------------------- helpers -------------------
DEV unsigned f2tf(float x) {
    unsigned u;
    asm("cvt.rna.tf32.f32 %0, %1;" : "=r"(u) : "f"(x));
    return u;
}

DEV void mma_tf32(float c[4], const unsigned a[4], const unsigned b[2]) {
    asm volatile(
        "mma.sync.aligned.m16n8k8.row.col.f32.tf32.tf32.f32 "
        "{%0,%1,%2,%3},{%4,%5,%6,%7},{%8,%9},{%0,%1,%2,%3};\n"
        : "+f"(c[0]), "+f"(c[1]), "+f"(c[2]), "+f"(c[3])
        : "r"(a[0]), "r"(a[1]), "r"(a[2]), "r"(a[3]), "r"(b[0]), "r"(b[1]));
}

// ------------------- 1) per-row mean / rstd of x -------------------
__global__ void __launch_bounds__(128) stats_x_kernel(const float* __restrict__ x) {
    int r = blockIdx.x;
    const float4* xr = (const float4*)(x + (size_t)r * D);
    int t = threadIdx.x;
    float4 a = xr[t];
    float4 b = xr[t + 128];
    float s  = a.x + a.y + a.z + a.w + b.x + b.y + b.z + b.w;
    float ss = a.x * a.x + a.y * a.y + a.z * a.z + a.w * a.w
             + b.x * b.x + b.y * b.y + b.z * b.z + b.w * b.w;
    #pragma unroll
    for (int o = 16; o; o >>= 1) {
        s  += __shfl_xor_sync(0xffffffffu, s, o);
        ss += __shfl_xor_sync(0xffffffffu, ss, o);
    }
    __shared__ float sh[8];
    int w = t >> 5;
    if ((t & 31) == 0) { sh[w] = s; sh[w + 4] = ss; }
    __syncthreads();
    if (t == 0) {
        s  = sh[0] + sh[1] + sh[2] + sh[3];
        ss = sh[4] + sh[5] + sh[6] + sh[7];
        float mu = s * (1.f / D);
        float var = ss * (1.f / D) - mu * mu;
        g_mu[r] = mu;
        g_rstd[r] = rsqrtf(var + LN_EPS);
    }
}

// ------------------- 2) latent layernorm -------------------
__global__ void __launch_bounds__(256) ln_lat_kernel(const float* __restrict__ lat,
                                                     const float* __restrict__ gl,
                                                     const float* __restrict__ bl) {
    int r = blockIdx.x;
    int t = threadIdx.x;
    const float4* xr = (const float4*)(lat + (size_t)r * D);
    float4 a = xr[t];
    float s  = a.x + a.y + a.z + a.w;
    float ss = a.x * a.x + a.y * a.y + a.z * a.z + a.w * a.w;
    #pragma unroll
    for (int o = 16; o; o >>= 1) {
        s  += __shfl_xor_sync(0xffffffffu, s, o);
        ss += __shfl_xor_sync(0xffffffffu, ss, o);
    }
    __shared__ float sh[18];
    int w = t >> 5;
    if ((t & 31) == 0) { sh[w] = s; sh[8 + w] = ss; }
    __syncthreads();
    if (t == 0) {
        s = 0.f; ss = 0.f;
        #pragma unroll
        for (int i = 0; i < 8; i++) { s += sh[i]; ss += sh[8 + i]; }
        float mu = s * (1.f / D);
        float var = ss * (1.f / D) - mu * mu;
        sh[16] = mu;
        sh[17] = rsqrtf(var + LN_EPS);
    }
    __syncthreads();
    float mu = sh[16], rs = sh[17];
    float4 g4 = ((const float4*)gl)[t];
    float4 b4 = ((const float4*)bl)[t];
    float4 o;
    o.x = (a.x - mu) * rs * g4.x + b4.x;
    o.y = (a.y - mu) * rs * g4.y + b4.y;
    o.z = (a.z - mu) * rs * g4.z + b4.z;
    o.w = (a.w - mu) * rs * g4.w + b4.w;
    ((float4*)(g_latln + (size_t)r * D))[t] = o;
}

// ------------------- 3) fused prep: bcat + per-d-tile partial colsums -------------------
// grid 64 (d-tiles of 16 rows), 256 threads; thread owns 4 consecutive j columns.
__global__ void __launch_bounds__(256) prep2(const float* __restrict__ Wk,
                                             const float* __restrict__ Wv,
                                             const float* __restrict__ gm,
                                             const float* __restrict__ bm) {
    int d0 = blockIdx.x * 16;
    int j = threadIdx.x * 4;
    const float* W = (j < 512) ? Wk : Wv;
    int jl = (j < 512) ? j : (j - 512);
    float pc0 = 0.f, pc1 = 0.f, pc2 = 0.f, pc3 = 0.f;
    float pb0 = 0.f, pb1 = 0.f, pb2 = 0.f, pb3 = 0.f;
    #pragma unroll 4
    for (int dd = 0; dd < 16; dd++) {
        int d = d0 + dd;
        float g = gm[d], be = bm[d];
        float4 w = *reinterpret_cast<const float4*>(W + (size_t)d * 512 + jl);
        float4 gw = make_float4(g * w.x, g * w.y, g * w.z, g * w.w);
        *reinterpret_cast<float4*>(g_bcat + (size_t)d * 1024 + j) = gw;
        pc0 += gw.x; pc1 += gw.y; pc2 += gw.z; pc3 += gw.w;
        pb0 += be * w.x; pb1 += be * w.y; pb2 += be * w.z; pb3 += be * w.w;
    }
    float4* pcw = reinterpret_cast<float4*>(g_partc + blockIdx.x * 1024 + j);
    float4* pbw = reinterpret_cast<float4*>(g_partb + blockIdx.x * 1024 + j);
    *pcw = make_float4(pc0, pc1, pc2, pc3);
    *pbw = make_float4(pb0, pb1, pb2, pb3);
}

__global__ void __launch_bounds__(256) sum_parts() {
    int j = blockIdx.x * 256 + threadIdx.x;
    float c = 0.f, b = 0.f;
    #pragma unroll
    for (int i = 0; i < 64; i++) {
        c += g_partc[i * 1024 + j];
        b += g_partb[i * 1024 + j];
    }
    g_csum[j] = c;
    g_bsum[j] = b;
}

// ------------------- 4) big fused K/V GEMM (tf32 mma, LN epilogue) -------------------
// C[65536 x 1024] = x @ Bcat ; epilogue: rstd*(acc - mu*csum) + bsum -> g_k / g_v
__global__ void __launch_bounds__(256) gemm_kv(const float* __restrict__ x) {
    extern __shared__ unsigned smem_[];
    unsigned* As = smem_;                    // [2][128*APITCH]
    unsigned* Bs = smem_ + 2 * ASZ;          // [2][32*BPITCH]
    const int tid = threadIdx.x, warp = tid >> 5, lane = tid & 31;
    const int g = lane >> 2, tg = lane & 3;
    const int wm = warp >> 2, wn = warp & 3;
    const int m0 = blockIdx.y * 128, n0 = blockIdx.x * 128;

    float acc[4][4][4];
    #pragma unroll
    for (int a = 0; a < 4; a++)
        #pragma unroll
        for (int b = 0; b < 4; b++)
            #pragma unroll
            for (int c = 0; c < 4; c++) acc[a][b][c] = 0.f;

    const int ar = tid >> 3;          // + i*32
    const int ac = (tid & 7) * 4;
    const int br = tid >> 5;          // + i*8
    const int bc = (tid & 31) * 4;

    float4 pa[4], pb[4];
    #pragma unroll
    for (int i = 0; i < 4; i++)
        pa[i] = *reinterpret_cast<const float4*>(x + (size_t)(m0 + ar + i * 32) * 1024 + ac);
    #pragma unroll
    for (int i = 0; i < 4; i++)
        pb[i] = *reinterpret_cast<const float4*>(g_bcat + (size_t)(br + i * 8) * 1024 + n0 + bc);
    #pragma unroll
    for (int i = 0; i < 4; i++) {
        float4 r;
        r.x = __uint_as_float(f2tf(pa[i].x)); r.y = __uint_as_float(f2tf(pa[i].y));
        r.z = __uint_as_float(f2tf(pa[i].z)); r.w = __uint_as_float(f2tf(pa[i].w));
        *reinterpret_cast<float4*>(As + (ar + i * 32) * APITCH + ac) = r;
    }
    #pragma unroll
    for (int i = 0; i < 4; i++) {
        float4 r;
        r.x = __uint_as_float(f2tf(pb[i].x)); r.y = __uint_as_float(f2tf(pb[i].y));
        r.z = __uint_as_float(f2tf(pb[i].z)); r.w = __uint_as_float(f2tf(pb[i].w));
        *reinterpret_cast<float4*>(Bs + (br + i * 8) * BPITCH + bc) = r;
    }
    __syncthreads();

    int cur = 0;
    for (int kt = 0; kt < 32; kt++) {
        if (kt < 31) {
            int k0 = (kt + 1) * 32;
            #pragma unroll
            for (int i = 0; i < 4; i++)
                pa[i] = *reinterpret_cast<const float4*>(x + (size_t)(m0 + ar + i * 32) * 1024 + k0 + ac);
            #pragma unroll
            for (int i = 0; i < 4; i++)
                pb[i] = *reinterpret_cast<const float4*>(g_bcat + (size_t)(k0 + br + i * 8) * 1024 + n0 + bc);
        }
        const unsigned* A_ = As + cur * ASZ;
        const unsigned* B_ = Bs + cur * BSZ;
        #pragma unroll
        for (int ks = 0; ks < 4; ks++) {
            const int k = ks * 8;
            unsigned af[4][4], bf[4][2];
            #pragma unroll
            for (int mf = 0; mf < 4; mf++) {
                const int r = wm * 64 + mf * 16;
                af[mf][0] = A_[(r + g) * APITCH + k + tg];
                af[mf][1] = A_[(r + g + 8) * APITCH + k + tg];
                af[mf][2] = A_[(r + g) * APITCH + k + tg + 4];
                af[mf][3] = A_[(r + g + 8) * APITCH + k + tg + 4];
            }
            #pragma unroll
            for (int nf = 0; nf < 4; nf++) {
                const int c = wn * 32 + nf * 8;
                bf[nf][0] = B_[(k + tg) * BPITCH + c + g];
                bf[nf][1] = B_[(k + tg + 4) * BPITCH + c + g];
            }
            #pragma unroll
            for (int mf = 0; mf < 4; mf++)
                #pragma unroll
                for (int nf = 0; nf < 4; nf++)
                    mma_tf32(acc[mf][nf], af[mf], bf[nf]);
        }
        if (kt < 31) {
            cur ^= 1;
            unsigned* Aw = As + cur * ASZ;
            unsigned* Bw = Bs + cur * BSZ;
            #pragma unroll
            for (int i = 0; i < 4; i++) {
                float4 r;
                r.x = __uint_as_float(f2tf(pa[i].x)); r.y = __uint_as_float(f2tf(pa[i].y));
                r.z = __uint_as_float(f2tf(pa[i].z)); r.w = __uint_as_float(f2tf(pa[i].w));
                *reinterpret_cast<float4*>(Aw + (ar + i * 32) * APITCH + ac) = r;
            }
            #pragma unroll
            for (int i = 0; i < 4; i++) {
                float4 r;
                r.x = __uint_as_float(f2tf(pb[i].x)); r.y = __uint_as_float(f2tf(pb[i].y));
                r.z = __uint_as_float(f2tf(pb[i].z)); r.w = __uint_as_float(f2tf(pb[i].w));
                *reinterpret_cast<float4*>(Bw + (br + i * 8) * BPITCH + bc) = r;
            }
            __syncthreads();
        }
    }

    // epilogue: fold layernorm, split K / V, remap rows b*8192+fi -> b*8256+fi
    #pragma unroll
    for (int mf = 0; mf < 4; mf++) {
        int r0 = m0 + wm * 64 + mf * 16 + g;
        int r1 = r0 + 8;
        float mu0 = g_mu[r0], rs0 = g_rstd[r0];
        float mu1 = g_mu[r1], rs1 = g_rstd[r1];
        size_t ro0 = (size_t)((r0 >> 13) * 8256 + (r0 & 8191));
        size_t ro1 = (size_t)((r1 >> 13) * 8256 + (r1 & 8191));
        #pragma unroll
        for (int nf = 0; nf < 4; nf++) {
            int c0 = n0 + wn * 32 + nf * 8 + 2 * tg;
            #pragma unroll
            for (int jj = 0; jj < 2; jj++) {
                int j = c0 + jj;
                float cs = g_csum[j], bs2 = g_bsum[j];
                float v0 = rs0 * (acc[mf][nf][jj] - mu0 * cs) + bs2;
                float v1 = rs1 * (acc[mf][nf][2 + jj] - mu1 * cs) + bs2;
                if (j < 512) {
                    g_k[ro0 * 512 + j] = v0;
                    g_k[ro1 * 512 + j] = v1;
                } else {
                    g_v[ro0 * 512 + (j - 512)] = v0;
                    g_v[ro1 * 512 + (j - 512)] = v1;
                }
            }
        }
    }
}

// ------------------- 5) latent Q/K/V GEMM (fp32 FFMA, small) -------------------
__global__ void __launch_bounds__(256) gemm_lat(const float* __restrict__ Wq,
                                                const float* __restrict__ Wk,
                                                const float* __restrict__ Wv,
                                                const float* __restrict__ kvg) {
    __shared__ float as_[64][17];
    __shared__ float bs_[16][65];
    int t = threadIdx.x;
    int n0 = blockIdx.x * 64, m0 = blockIdx.y * 64;
    int w = n0 >> 9;
    int nj0 = n0 & 511;
    const float* W = (w == 0) ? Wq : ((w == 1) ? Wk : Wv);
    int tx = t & 15, ty = t >> 4;
    float c[4][4] = {};
    for (int k0 = 0; k0 < 1024; k0 += 16) {
        #pragma unroll
        for (int i = 0; i < 4; i++) {
            int id = t + i * 256;
            as_[id >> 4][id & 15] = g_latln[(size_t)(m0 + (id >> 4)) * 1024 + k0 + (id & 15)];
        }
        #pragma unroll
        for (int i = 0; i < 4; i++) {
            int id = t + i * 256;
            bs_[id >> 6][id & 63] = W[(size_t)(k0 + (id >> 6)) * 512 + nj0 + (id & 63)];
        }
        __syncthreads();
        #pragma unroll
        for (int kk = 0; kk < 16; kk++) {
            float ra[4], rb[4];
            #pragma unroll
            for (int i = 0; i < 4; i++) ra[i] = as_[ty + 16 * i][kk];
            #pragma unroll
            for (int j = 0; j < 4; j++) rb[j] = bs_[kk][tx + 16 * j];
            #pragma unroll
            for (int i = 0; i < 4; i++)
                #pragma unroll
                for (int j = 0; j < 4; j++) c[i][j] += ra[i] * rb[j];
        }
        __syncthreads();
    }
    float gate = *kvg;
    #pragma unroll
    for (int i = 0; i < 4; i++)
        #pragma unroll
        for (int j = 0; j < 4; j++) {
            int m = m0 + ty + 16 * i;
            int J = n0 + tx + 16 * j;
            int b = m >> 6, li = m & 63;
            float v = c[i][j];
            if (w == 0) {
                g_q[(size_t)m * 512 + J] = v * QSCALE;
            } else if (w == 1) {
                g_k[((size_t)(b * 8256 + 8192 + li)) * 512 + (J - 512)] = v * gate;
            } else {
                g_v[((size_t)(b * 8256 + 8192 + li)) * 512 + (J - 1024)] = v * gate;
            }
        }
}

// ------------------- 6) split-KV flash attention (fp32, online softmax) -------------------
__global__ void __launch_bounds__(256) attn_kernel(const int* __restrict__ mask) {
    __shared__ float qs[64][65];
    __shared__ float ks[32][65];
    __shared__ float vs[32][65];
    __shared__ float ss[64][33];

    const int s = blockIdx.x, h = blockIdx.y, b = blockIdx.z;
    const int t = threadIdx.x;
    const int qr = t >> 2, part = t & 3;

    #pragma unroll
    for (int i = 0; i < 4; i++) {
        int id = t + i * 256;
        int r = id >> 4, c4 = id & 15;
        float4 q4 = *reinterpret_cast<const float4*>(
            g_q + (size_t)(b * 64 + r) * 512 + h * 64 + c4 * 4);
        qs[r][c4 * 4 + 0] = q4.x; qs[r][c4 * 4 + 1] = q4.y;
        qs[r][c4 * 4 + 2] = q4.z; qs[r][c4 * 4 + 3] = q4.w;
    }

    float m = -1e30f, l = 0.f;
    float acc[16];
    #pragma unroll
    for (int i = 0; i < 16; i++) acc[i] = 0.f;

    const int base = s * SPLEN;
    for (int k0 = 0; k0 < SPLEN; k0 += 32) {
        int nrows = min(32, SPLEN - k0);
        __syncthreads();
        #pragma unroll
        for (int i = 0; i < 2; i++) {
            int id = t + i * 256;
            int r = id >> 4, c4 = id & 15;
            if (r < nrows) {
                size_t ro = (size_t)(b * 8256 + base + k0 + r) * 512 + h * 64 + c4 * 4;
                float4 k4 = *reinterpret_cast<const float4*>(g_k + ro);
                float4 v4 = *reinterpret_cast<const float4*>(g_v + ro);
                ks[r][c4 * 4 + 0] = k4.x; ks[r][c4 * 4 + 1] = k4.y;
                ks[r][c4 * 4 + 2] = k4.z; ks[r][c4 * 4 + 3] = k4.w;
                vs[r][c4 * 4 + 0] = v4.x; vs[r][c4 * 4 + 1] = v4.y;
                vs[r][c4 * 4 + 2] = v4.z; vs[r][c4 * 4 + 3] = v4.w;
            } else {
                ks[r][c4 * 4 + 0] = 0.f; ks[r][c4 * 4 + 1] = 0.f;
                ks[r][c4 * 4 + 2] = 0.f; ks[r][c4 * 4 + 3] = 0.f;
                vs[r][c4 * 4 + 0] = 0.f; vs[r][c4 * 4 + 1] = 0.f;
                vs[r][c4 * 4 + 2] = 0.f; vs[r][c4 * 4 + 3] = 0.f;
            }
        }
        __syncthreads();
        #pragma unroll
        for (int i = 0; i < 8; i++) {
            int id = t + i * 256;
            int qr2 = id >> 5, kr = id & 31;
            int pos = base + k0 + kr;
            bool valid = (kr < nrows) && (pos >= F || mask[b * F + pos] == 0);
            float sc = -1e30f;
            if (valid) {
                sc = 0.f;
                #pragma unroll 8
                for (int c = 0; c < 64; c++) sc += qs[qr2][c] * ks[kr][c];
            }
            ss[qr2][kr] = sc;
        }
        __syncthreads();
        float cmax = -1e30f;
        #pragma unroll
        for (int k = 0; k < 32; k++) cmax = fmaxf(cmax, ss[qr][k]);
        float mn = fmaxf(m, cmax);
        float scale = __expf(m - mn);
        m = mn;
        l *= scale;
        #pragma unroll
        for (int c = 0; c < 16; c++) acc[c] *= scale;
        float lsum = 0.f;
        #pragma unroll 4
        for (int k = 0; k < 32; k++) {
            float sck = ss[qr][k];
            float p = (sck > -1e29f) ? __expf(sck - mn) : 0.f;
            lsum += p;
            #pragma unroll
            for (int c = 0; c < 16; c++) acc[c] += p * vs[k][part * 16 + c];
        }
        l += lsum;
    }

    int idx = ((b * 8 + h) * 8 + s) * 64 + qr;
    if (part == 0) { g_pm[idx] = m; g_pl[idx] = l; }
    #pragma unroll
    for (int c = 0; c < 16; c++)
        g_po[(size_t)idx * 64 + part * 16 + c] = acc[c];
}

// ------------------- 7) split combine -> y -------------------
__global__ void __launch_bounds__(128) combine_kernel() {
    int bq = blockIdx.x;
    int b = bq >> 6, qr = bq & 63;
    int t = threadIdx.x;
    int h = t >> 4, c0 = (t & 15) * 4;
    int idx0 = ((b * 8 + h) * 8) * 64 + qr;
    float M = -1e30f;
    #pragma unroll
    for (int s = 0; s < SPLITS; s++) M = fmaxf(M, g_pm[idx0 + s * 64]);
    float L = 0.f;
    float a[4] = {0.f, 0.f, 0.f, 0.f};
    #pragma unroll
    for (int s = 0; s < SPLITS; s++) {
        float w = __expf(g_pm[idx0 + s * 64] - M);
        L += g_pl[idx0 + s * 64] * w;
        size_t pb = (size_t)(idx0 + s * 64) * 64 + c0;
        #pragma unroll
        for (int j = 0; j < 4; j++) a[j] += g_po[pb + j] * w;
    }
    float inv = 1.f / L;
    size_t yo = (size_t)(b * 64 + qr) * 512 + h * 64 + c0;
    #pragma unroll
    for (int j = 0; j < 4; j++) g_y[yo + j] = a[j] * inv;
}

// ------------------- 8) output projection: out = y @ Wout -------------------
__global__ void __launch_bounds__(256) gemm_out(const float* __restrict__ Wout,
                                                float* __restrict__ out) {
    __shared__ float as_[64][17];
    __shared__ float bs_[16][65];
    int t = threadIdx.x;
    int n0 = blockIdx.x * 64, m0 = blockIdx.y * 64;
    int tx = t & 15, ty = t >> 4;
    float c[4][4] = {};
    for (int k0 = 0; k0 < 512; k0 += 16) {
        #pragma unroll
        for (int i = 0; i < 4; i++) {
            int id = t + i * 256;
            as_[id >> 4][id & 15] = g_y[(size_t)(m0 + (id >> 4)) * 512 + k0 + (id & 15)];
        }
        #pragma unroll
        for (int i = 0; i < 4; i++) {
            int id = t + i * 256;
            bs_[id >> 6][id & 63] = Wout[(size_t)(k0 + (id >> 6)) * 1024 + n0 + (id & 63)];
        }
        __syncthreads();
        #pragma unroll
        for (int kk = 0; kk < 16; kk++) {
            float ra[4], rb[4];
            #pragma unroll
            for (int i = 0; i < 4; i++) ra[i] = as_[ty + 16 * i][kk];
            #pragma unroll
            for (int j = 0; j < 4; j++) rb[j] = bs_[kk][tx + 16 * j];
            #pragma unroll
            for (int i = 0; i < 4; i++)
                #pragma unroll
                for (int j = 0; j < 4; j++) c[i][j] += ra[i] * rb[j];
        }
        __syncthreads();
    }
    #pragma unroll
    for (int i = 0; i < 4; i++)
        #pragma unroll
        for (int j = 0; j < 4; j++)
            out[(size_t)(m0 + ty + 16 * i) * 1024 + n0 + tx + 16 * j] = c[i][j];
}

// ------------------- launch -------------------
extern "C" void kernel_launch(void* const* d_in, const int* in_sizes, int n_in,
                              void* d_out, int out_size) {
    (void)in_sizes; (void)n_in; (void)out_size;
    const float* x   = (const float*)d_in[0];
    const float* lat = (const float*)d_in[1];
    const int*   mask = (const int*)d_in[2];          // bool -> int32 per harness contract
    const float* kvg = (const float*)d_in[3];
    const float* gm  = (const float*)d_in[4];
    const float* bm  = (const float*)d_in[5];
    const float* gl  = (const float*)d_in[6];
    const float* bl  = (const float*)d_in[7];
    const float* Wq  = (const float*)d_in[8];
    const float* Wk  = (const float*)d_in[9];
    const float* Wv  = (const float*)d_in[10];
    const float* Wout = (const float*)d_in[11];
    float* out = (float*)d_out;

    stats_x_kernel<<<ROWS_X, 128>>>(x);
    ln_lat_kernel<<<ROWS_L, 256>>>(lat, gl, bl);
    prep2<<<64, 256>>>(Wk, Wv, gm, bm);
    sum_parts<<<4, 256>>>();

    cudaFuncSetAttribute(gemm_kv, cudaFuncAttributeMaxDynamicSharedMemorySize, GEMM_SMEM);
    gemm_kv<<<dim3(8, 512), 256, GEMM_SMEM>>>(x);

    gemm_lat<<<dim3(24, 8), 256>>>(Wq, Wk, Wv, kvg);
    attn_kernel<<<dim3(SPLITS, H, Bb), 256>>>(mask);
    combine_kernel<<<512, 128>>>();
    gemm_out<<<dim3(16, 8), 256>>>(Wout, out);
}

// round 10
// speedup vs baseline: 1.7836x; 1.7836x over previous
#include <cuda_runtime.h>
#include <cuda_bf16.h>
#include <cstdint>
#include <cstddef>

#define DEV __device__ __forceinline__

namespace {
constexpr int Bb = 8, F = 8192, NL = 64, D = 1024, INNER = 512, H = 8, DH = 64;
constexpr int FN = F + NL;                 // 8256
constexpr int ROWS_X = Bb * F;             // 65536
constexpr int ROWS_L = Bb * NL;            // 512
constexpr int ROWS_KV = Bb * FN;           // 66048
constexpr float LN_EPS = 1e-5f;
constexpr float QSCALE = 0.125f;           // 64^-0.5
constexpr int SPLITS = 8;
constexpr int SPLEN = FN / SPLITS;         // 1032
constexpr int KV_SMEM = 2 * (4096 + 4096) * 4;   // 65536 B (2 stages x (A+B))
}

// ------------------- device scratch (static: no allocations allowed) -------------------
__device__ float g_mu[ROWS_X];
__device__ float g_rstd[ROWS_X];
__device__ float g_xr[(size_t)ROWS_X * D];        // tf32-rounded x
__device__ float g_latln[ROWS_L * D];
__device__ float g_bcatT[1024 * 1024];            // transposed gamma-folded [Wk|Wv]: [j][d], tf32-rounded
__device__ float g_partc[16 * 1024];
__device__ float g_partb[16 * 1024];
__device__ float g_csum[1024];
__device__ float g_bsum[1024];
__device__ float g_q[ROWS_L * INNER];
__device__ float g_k[(size_t)ROWS_KV * INNER];
__device__ float g_v[(size_t)ROWS_KV * INNER];
__device__ float g_y[ROWS_L * INNER];
__device__ float g_pm[Bb * H * SPLITS * NL];
__device__ float g_pl[Bb * H * SPLITS * NL];
__device__ float g_po[(size_t)Bb * H * SPLITS * NL * DH];

// ------------------- helpers -------------------
DEV unsigned f2tf(float x) {
    unsigned u;
    asm("cvt.rna.tf32.f32 %0, %1;" : "=r"(u) : "f"(x));
    return u;
}

DEV unsigned smem_u32(const void* p) {
    unsigned a;
    asm("{ .reg .u64 t; cvta.to.shared.u64 t, %1; cvt.u32.u64 %0, t; }" : "=r"(a) : "l"(p));
    return a;
}

DEV void cpa16(unsigned dst, const float* src) {
    asm volatile("cp.async.cg.shared.global [%0], [%1], 16;\n" :: "r"(dst), "l"(src) : "memory");
}

DEV void mma_tf32(float c[4], const unsigned a[4], const unsigned b[2]) {
    asm volatile(
        "mma.sync.aligned.m16n8k8.row.col.f32.tf32.tf32.f32 "
        "{%0,%1,%2,%3},{%4,%5,%6,%7},{%8,%9},{%0,%1,%2,%3};\n"
        : "+f"(c[0]), "+f"(c[1]), "+f"(c[2]), "+f"(c[3])
        : "r"(a[0]), "r"(a[1]), "r"(a[2]), "r"(a[3]), "r"(b[0]), "r"(b[1]));
}

// ------------------- 1) per-row mean / rstd of x + tf32-rounded copy -------------------
__global__ void __launch_bounds__(128) stats_x_kernel(const float* __restrict__ x) {
    int r = blockIdx.x;
    const float4* xr = (const float4*)(x + (size_t)r * D);
    int t = threadIdx.x;
    float4 a = xr[t];
    float4 b = xr[t + 128];
    float s  = a.x + a.y + a.z + a.w + b.x + b.y + b.z + b.w;
    float ss = a.x * a.x + a.y * a.y + a.z * a.z + a.w * a.w
             + b.x * b.x + b.y * b.y + b.z * b.z + b.w * b.w;
    float4 ra, rb;
    ra.x = __uint_as_float(f2tf(a.x)); ra.y = __uint_as_float(f2tf(a.y));
    ra.z = __uint_as_float(f2tf(a.z)); ra.w = __uint_as_float(f2tf(a.w));
    rb.x = __uint_as_float(f2tf(b.x)); rb.y = __uint_as_float(f2tf(b.y));
    rb.z = __uint_as_float(f2tf(b.z)); rb.w = __uint_as_float(f2tf(b.w));
    float4* xw = (float4*)(g_xr + (size_t)r * D);
    xw[t] = ra;
    xw[t + 128] = rb;
    #pragma unroll
    for (int o = 16; o; o >>= 1) {
        s  += __shfl_xor_sync(0xffffffffu, s, o);
        ss += __shfl_xor_sync(0xffffffffu, ss, o);
    }
    __shared__ float sh[8];
    int w = t >> 5;
    if ((t & 31) == 0) { sh[w] = s; sh[w + 4] = ss; }
    __syncthreads();
    if (t == 0) {
        s  = sh[0] + sh[1] + sh[2] + sh[3];
        ss = sh[4] + sh[5] + sh[6] + sh[7];
        float mu = s * (1.f / D);
        float var = ss * (1.f / D) - mu * mu;
        g_mu[r] = mu;
        g_rstd[r] = rsqrtf(var + LN_EPS);
    }
}

// ------------------- 2) latent layernorm -------------------
__global__ void __launch_bounds__(256) ln_lat_kernel(const float* __restrict__ lat,
                                                     const float* __restrict__ gl,
                                                     const float* __restrict__ bl) {
    int r = blockIdx.x;
    int t = threadIdx.x;
    const float4* xr = (const float4*)(lat + (size_t)r * D);
    float4 a = xr[t];
    float s  = a.x + a.y + a.z + a.w;
    float ss = a.x * a.x + a.y * a.y + a.z * a.z + a.w * a.w;
    #pragma unroll
    for (int o = 16; o; o >>= 1) {
        s  += __shfl_xor_sync(0xffffffffu, s, o);
        ss += __shfl_xor_sync(0xffffffffu, ss, o);
    }
    __shared__ float sh[18];
    int w = t >> 5;
    if ((t & 31) == 0) { sh[w] = s; sh[8 + w] = ss; }
    __syncthreads();
    if (t == 0) {
        s = 0.f; ss = 0.f;
        #pragma unroll
        for (int i = 0; i < 8; i++) { s += sh[i]; ss += sh[8 + i]; }
        float mu = s * (1.f / D);
        float var = ss * (1.f / D) - mu * mu;
        sh[16] = mu;
        sh[17] = rsqrtf(var + LN_EPS);
    }
    __syncthreads();
    float mu = sh[16], rs = sh[17];
    float4 g4 = ((const float4*)gl)[t];
    float4 b4 = ((const float4*)bl)[t];
    float4 o;
    o.x = (a.x - mu) * rs * g4.x + b4.x;
    o.y = (a.y - mu) * rs * g4.y + b4.y;
    o.z = (a.z - mu) * rs * g4.z + b4.z;
    o.w = (a.w - mu) * rs * g4.w + b4.w;
    ((float4*)(g_latln + (size_t)r * D))[t] = o;
}

// ------------------- 3) prep: transpose + gamma-fold (tf32) + partial colsums -------------------
// grid (16 j-tiles, 16 d-tiles), 256 threads; 64d x 64j tile per block.
__global__ void __launch_bounds__(256) prep_t(const float* __restrict__ Wk,
                                              const float* __restrict__ Wv,
                                              const float* __restrict__ gm,
                                              const float* __restrict__ bm) {
    __shared__ float sg[64][65];
    __shared__ float redc[4][64];
    __shared__ float redb[4][64];
    int t = threadIdx.x;
    int j0 = blockIdx.x * 64, d0 = blockIdx.y * 64;
    int jc = t & 63;
    int j = j0 + jc;
    const float* W = (j < 512) ? Wk : Wv;
    int jl = (j < 512) ? j : (j - 512);
    float pc = 0.f, pb = 0.f;
    #pragma unroll
    for (int i = 0; i < 16; i++) {
        int dr = (t >> 6) + i * 4;
        int d = d0 + dr;
        float w = W[(size_t)d * 512 + jl];
        float gv = __uint_as_float(f2tf(gm[d] * w));
        sg[dr][jc] = gv;
        pc += gv;
        pb += bm[d] * w;
    }
    redc[t >> 6][jc] = pc;
    redb[t >> 6][jc] = pb;
    __syncthreads();
    if (t < 64) {
        float c = redc[0][t] + redc[1][t] + redc[2][t] + redc[3][t];
        float b = redb[0][t] + redb[1][t] + redb[2][t] + redb[3][t];
        g_partc[blockIdx.y * 1024 + j0 + t] = c;
        g_partb[blockIdx.y * 1024 + j0 + t] = b;
    }
    // transposed write: g_bcatT[j][d]
    #pragma unroll
    for (int i = 0; i < 16; i++) {
        int jr = (t >> 6) + i * 4;
        int dc = t & 63;
        g_bcatT[(size_t)(j0 + jr) * 1024 + d0 + dc] = sg[dc][jr];
    }
}

__global__ void __launch_bounds__(256) sum_parts() {
    int j = blockIdx.x * 256 + threadIdx.x;
    float c = 0.f, b = 0.f;
    #pragma unroll
    for (int i = 0; i < 16; i++) {
        c += g_partc[i * 1024 + j];
        b += g_partb[i * 1024 + j];
    }
    g_csum[j] = c;
    g_bsum[j] = b;
}

// ------------------- 4) big fused K/V GEMM: conflict-free swizzled smem + cp.async -------------------
// A: x rows (128m x 32k), B: g_bcatT rows (128n x 32k), both 8 atoms/row, atom^(row&7) swizzle.
DEV void kv_load_stage(unsigned sbase, int tid, int kt, int s, int m0, int n0) {
    int k0 = kt * 32;
    unsigned abase = sbase + (unsigned)s * 32768u;
    unsigned bbase = abase + 16384u;
    int row = tid >> 3;                 // + i*32
    int atom = tid & 7;
    #pragma unroll
    for (int i = 0; i < 4; i++) {
        int r = row + i * 32;
        unsigned off = (unsigned)(r * 32 + ((atom ^ (r & 7)) << 2)) * 4u;
        cpa16(abase + off, g_xr + (size_t)(m0 + r) * 1024 + k0 + atom * 4);
        cpa16(bbase + off, g_bcatT + (size_t)(n0 + r) * 1024 + k0 + atom * 4);
    }
    asm volatile("cp.async.commit_group;\n" ::: "memory");
}

__global__ void __launch_bounds__(256) gemm_kv() {
    extern __shared__ unsigned sm[];
    unsigned sbase = smem_u32(sm);
    const int tid = threadIdx.x, warp = tid >> 5, lane = tid & 31;
    const int g = lane >> 2, tg = lane & 3;
    const int wm = warp >> 2, wn = warp & 3;
    const int m0 = blockIdx.y * 128, n0 = blockIdx.x * 128;

    float acc[4][4][4];
    #pragma unroll
    for (int a = 0; a < 4; a++)
        #pragma unroll
        for (int b = 0; b < 4; b++)
            #pragma unroll
            for (int c = 0; c < 4; c++) acc[a][b][c] = 0.f;

    kv_load_stage(sbase, tid, 0, 0, m0, n0);
    kv_load_stage(sbase, tid, 1, 1, m0, n0);

    for (int kt = 0; kt < 32; kt++) {
        const int s = kt & 1;
        if (kt < 31) asm volatile("cp.async.wait_group 1;\n" ::: "memory");
        else         asm volatile("cp.async.wait_group 0;\n" ::: "memory");
        __syncthreads();

        const unsigned* A_ = sm + s * 8192;
        const unsigned* B_ = A_ + 4096;
        #pragma unroll
        for (int ks = 0; ks < 4; ks++) {
            const int ks2 = ks * 2;
            const int x0 = ((ks2 ^ g) << 2) + tg;
            const int x1 = (((ks2 + 1) ^ g) << 2) + tg;
            unsigned af[4][4], bf[4][2];
            #pragma unroll
            for (int mf = 0; mf < 4; mf++) {
                const int r0 = (wm * 64 + mf * 16 + g) * 32;
                af[mf][0] = A_[r0 + x0];
                af[mf][1] = A_[r0 + 256 + x0];     // +8 rows * 32
                af[mf][2] = A_[r0 + x1];
                af[mf][3] = A_[r0 + 256 + x1];
            }
            #pragma unroll
            for (int nf = 0; nf < 4; nf++) {
                const int b0 = (wn * 32 + nf * 8 + g) * 32;
                bf[nf][0] = B_[b0 + x0];
                bf[nf][1] = B_[b0 + x1];
            }
            #pragma unroll
            for (int mf = 0; mf < 4; mf++)
                #pragma unroll
                for (int nf = 0; nf < 4; nf++)
                    mma_tf32(acc[mf][nf], af[mf], bf[nf]);
        }

        if (kt < 30) {
            __syncthreads();
            kv_load_stage(sbase, tid, kt + 2, s, m0, n0);
        }
    }

    // epilogue: fold layernorm, split K / V, remap rows b*8192+fi -> b*8256+fi
    #pragma unroll
    for (int mf = 0; mf < 4; mf++) {
        int r0 = m0 + wm * 64 + mf * 16 + g;
        int r1 = r0 + 8;
        float mu0 = g_mu[r0], rs0 = g_rstd[r0];
        float mu1 = g_mu[r1], rs1 = g_rstd[r1];
        size_t ro0 = (size_t)((r0 >> 13) * 8256 + (r0 & 8191));
        size_t ro1 = (size_t)((r1 >> 13) * 8256 + (r1 & 8191));
        #pragma unroll
        for (int nf = 0; nf < 4; nf++) {
            int c0 = n0 + wn * 32 + nf * 8 + 2 * tg;
            #pragma unroll
            for (int jj = 0; jj < 2; jj++) {
                int j = c0 + jj;
                float cs = g_csum[j], bs2 = g_bsum[j];
                float v0 = rs0 * (acc[mf][nf][jj] - mu0 * cs) + bs2;
                float v1 = rs1 * (acc[mf][nf][2 + jj] - mu1 * cs) + bs2;
                if (j < 512) {
                    g_k[ro0 * 512 + j] = v0;
                    g_k[ro1 * 512 + j] = v1;
                } else {
                    g_v[ro0 * 512 + (j - 512)] = v0;
                    g_v[ro1 * 512 + (j - 512)] = v1;
                }
            }
        }
    }
}

// ------------------- 5) latent Q/K/V GEMM (fp32 FFMA, small) -------------------
__global__ void __launch_bounds__(256) gemm_lat(const float* __restrict__ Wq,
                                                const float* __restrict__ Wk,
                                                const float* __restrict__ Wv,
                                                const float* __restrict__ kvg) {
    __shared__ float as_[64][17];
    __shared__ float bs_[16][65];
    int t = threadIdx.x;
    int n0 = blockIdx.x * 64, m0 = blockIdx.y * 64;
    int w = n0 >> 9;
    int nj0 = n0 & 511;
    const float* W = (w == 0) ? Wq : ((w == 1) ? Wk : Wv);
    int tx = t & 15, ty = t >> 4;
    float c[4][4] = {};
    for (int k0 = 0; k0 < 1024; k0 += 16) {
        #pragma unroll
        for (int i = 0; i < 4; i++) {
            int id = t + i * 256;
            as_[id >> 4][id & 15] = g_latln[(size_t)(m0 + (id >> 4)) * 1024 + k0 + (id & 15)];
        }
        #pragma unroll
        for (int i = 0; i < 4; i++) {
            int id = t + i * 256;
            bs_[id >> 6][id & 63] = W[(size_t)(k0 + (id >> 6)) * 512 + nj0 + (id & 63)];
        }
        __syncthreads();
        #pragma unroll
        for (int kk = 0; kk < 16; kk++) {
            float ra[4], rb[4];
            #pragma unroll
            for (int i = 0; i < 4; i++) ra[i] = as_[ty + 16 * i][kk];
            #pragma unroll
            for (int j = 0; j < 4; j++) rb[j] = bs_[kk][tx + 16 * j];
            #pragma unroll
            for (int i = 0; i < 4; i++)
                #pragma unroll
                for (int j = 0; j < 4; j++) c[i][j] += ra[i] * rb[j];
        }
        __syncthreads();
    }
    float gate = *kvg;
    #pragma unroll
    for (int i = 0; i < 4; i++)
        #pragma unroll
        for (int j = 0; j < 4; j++) {
            int m = m0 + ty + 16 * i;
            int J = n0 + tx + 16 * j;
            int b = m >> 6, li = m & 63;
            float v = c[i][j];
            if (w == 0) {
                g_q[(size_t)m * 512 + J] = v * QSCALE;
            } else if (w == 1) {
                g_k[((size_t)(b * 8256 + 8192 + li)) * 512 + (J - 512)] = v * gate;
            } else {
                g_v[((size_t)(b * 8256 + 8192 + li)) * 512 + (J - 1024)] = v * gate;
            }
        }
}

// ------------------- 6) split-KV flash attention (fp32, online softmax) -------------------
__global__ void __launch_bounds__(256) attn_kernel(const int* __restrict__ mask) {
    __shared__ float qs[64][65];
    __shared__ float ks[32][65];
    __shared__ float vs[32][65];
    __shared__ float ss[64][33];

    const int s = blockIdx.x, h = blockIdx.y, b = blockIdx.z;
    const int t = threadIdx.x;
    const int qr = t >> 2, part = t & 3;

    #pragma unroll
    for (int i = 0; i < 4; i++) {
        int id = t + i * 256;
        int r = id >> 4, c4 = id & 15;
        float4 q4 = *reinterpret_cast<const float4*>(
            g_q + (size_t)(b * 64 + r) * 512 + h * 64 + c4 * 4);
        qs[r][c4 * 4 + 0] = q4.x; qs[r][c4 * 4 + 1] = q4.y;
        qs[r][c4 * 4 + 2] = q4.z; qs[r][c4 * 4 + 3] = q4.w;
    }

    float m = -1e30f, l = 0.f;
    float acc[16];
    #pragma unroll
    for (int i = 0; i < 16; i++) acc[i] = 0.f;

    const int base = s * SPLEN;
    for (int k0 = 0; k0 < SPLEN; k0 += 32) {
        int nrows = min(32, SPLEN - k0);
        __syncthreads();
        #pragma unroll
        for (int i = 0; i < 2; i++) {
            int id = t + i * 256;
            int r = id >> 4, c4 = id & 15;
            if (r < nrows) {
                size_t ro = (size_t)(b * 8256 + base + k0 + r) * 512 + h * 64 + c4 * 4;
                float4 k4 = *reinterpret_cast<const float4*>(g_k + ro);
                float4 v4 = *reinterpret_cast<const float4*>(g_v + ro);
                ks[r][c4 * 4 + 0] = k4.x; ks[r][c4 * 4 + 1] = k4.y;
                ks[r][c4 * 4 + 2] = k4.z; ks[r][c4 * 4 + 3] = k4.w;
                vs[r][c4 * 4 + 0] = v4.x; vs[r][c4 * 4 + 1] = v4.y;
                vs[r][c4 * 4 + 2] = v4.z; vs[r][c4 * 4 + 3] = v4.w;
            } else {
                ks[r][c4 * 4 + 0] = 0.f; ks[r][c4 * 4 + 1] = 0.f;
                ks[r][c4 * 4 + 2] = 0.f; ks[r][c4 * 4 + 3] = 0.f;
                vs[r][c4 * 4 + 0] = 0.f; vs[r][c4 * 4 + 1] = 0.f;
                vs[r][c4 * 4 + 2] = 0.f; vs[r][c4 * 4 + 3] = 0.f;
            }
        }
        __syncthreads();
        #pragma unroll
        for (int i = 0; i < 8; i++) {
            int id = t + i * 256;
            int qr2 = id >> 5, kr = id & 31;
            int pos = base + k0 + kr;
            bool valid = (kr < nrows) && (pos >= F || mask[b * F + pos] == 0);
            float sc = -1e30f;
            if (valid) {
                sc = 0.f;
                #pragma unroll 8
                for (int c = 0; c < 64; c++) sc += qs[qr2][c] * ks[kr][c];
            }
            ss[qr2][kr] = sc;
        }
        __syncthreads();
        float cmax = -1e30f;
        #pragma unroll
        for (int k = 0; k < 32; k++) cmax = fmaxf(cmax, ss[qr][k]);
        float mn = fmaxf(m, cmax);
        float scale = __expf(m - mn);
        m = mn;
        l *= scale;
        #pragma unroll
        for (int c = 0; c < 16; c++) acc[c] *= scale;
        float lsum = 0.f;
        #pragma unroll 4
        for (int k = 0; k < 32; k++) {
            float sck = ss[qr][k];
            float p = (sck > -1e29f) ? __expf(sck - mn) : 0.f;
            lsum += p;
            #pragma unroll
            for (int c = 0; c < 16; c++) acc[c] += p * vs[k][part * 16 + c];
        }
        l += lsum;
    }

    int idx = ((b * 8 + h) * 8 + s) * 64 + qr;
    if (part == 0) { g_pm[idx] = m; g_pl[idx] = l; }
    #pragma unroll
    for (int c = 0; c < 16; c++)
        g_po[(size_t)idx * 64 + part * 16 + c] = acc[c];
}

// ------------------- 7) split combine -> y -------------------
__global__ void __launch_bounds__(128) combine_kernel() {
    int bq = blockIdx.x;
    int b = bq >> 6, qr = bq & 63;
    int t = threadIdx.x;
    int h = t >> 4, c0 = (t & 15) * 4;
    int idx0 = ((b * 8 + h) * 8) * 64 + qr;
    float M = -1e30f;
    #pragma unroll
    for (int s = 0; s < SPLITS; s++) M = fmaxf(M, g_pm[idx0 + s * 64]);
    float L = 0.f;
    float a[4] = {0.f, 0.f, 0.f, 0.f};
    #pragma unroll
    for (int s = 0; s < SPLITS; s++) {
        float w = __expf(g_pm[idx0 + s * 64] - M);
        L += g_pl[idx0 + s * 64] * w;
        size_t pb = (size_t)(idx0 + s * 64) * 64 + c0;
        #pragma unroll
        for (int j = 0; j < 4; j++) a[j] += g_po[pb + j] * w;
    }
    float inv = 1.f / L;
    size_t yo = (size_t)(b * 64 + qr) * 512 + h * 64 + c0;
    #pragma unroll
    for (int j = 0; j < 4; j++) g_y[yo + j] = a[j] * inv;
}

// ------------------- 8) output projection: out = y @ Wout -------------------
__global__ void __launch_bounds__(256) gemm_out(const float* __restrict__ Wout,
                                                float* __restrict__ out) {
    __shared__ float as_[64][17];
    __shared__ float bs_[16][65];
    int t = threadIdx.x;
    int n0 = blockIdx.x * 64, m0 = blockIdx.y * 64;
    int tx = t & 15, ty = t >> 4;
    float c[4][4] = {};
    for (int k0 = 0; k0 < 512; k0 += 16) {
        #pragma unroll
        for (int i = 0; i < 4; i++) {
            int id = t + i * 256;
            as_[id >> 4][id & 15] = g_y[(size_t)(m0 + (id >> 4)) * 512 + k0 + (id & 15)];
        }
        #pragma unroll
        for (int i = 0; i < 4; i++) {
            int id = t + i * 256;
            bs_[id >> 6][id & 63] = Wout[(size_t)(k0 + (id >> 6)) * 1024 + n0 + (id & 63)];
        }
        __syncthreads();
        #pragma unroll
        for (int kk = 0; kk < 16; kk++) {
            float ra[4], rb[4];
            #pragma unroll
            for (int i = 0; i < 4; i++) ra[i] = as_[ty + 16 * i][kk];
            #pragma unroll
            for (int j = 0; j < 4; j++) rb[j] = bs_[kk][tx + 16 * j];
            #pragma unroll
            for (int i = 0; i < 4; i++)
                #pragma unroll
                for (int j = 0; j < 4; j++) c[i][j] += ra[i] * rb[j];
        }
        __syncthreads();
    }
    #pragma unroll
    for (int i = 0; i < 4; i++)
        #pragma unroll
        for (int j = 0; j < 4; j++)
            out[(size_t)(m0 + ty + 16 * i) * 1024 + n0 + tx + 16 * j] = c[i][j];
}

// ------------------- launch -------------------
extern "C" void kernel_launch(void* const* d_in, const int* in_sizes, int n_in,
                              void* d_out, int out_size) {
    (void)in_sizes; (void)n_in; (void)out_size;
    const float* x   = (const float*)d_in[0];
    const float* lat = (const float*)d_in[1];
    const int*   mask = (const int*)d_in[2];          // bool -> int32 per harness contract
    const float* kvg = (const float*)d_in[3];
    const float* gm  = (const float*)d_in[4];
    const float* bm  = (const float*)d_in[5];
    const float* gl  = (const float*)d_in[6];
    const float* bl  = (const float*)d_in[7];
    const float* Wq  = (const float*)d_in[8];
    const float* Wk  = (const float*)d_in[9];
    const float* Wv  = (const float*)d_in[10];
    const float* Wout = (const float*)d_in[11];
    float* out = (float*)d_out;

    stats_x_kernel<<<ROWS_X, 128>>>(x);
    prep_t<<<dim3(16, 16), 256>>>(Wk, Wv, gm, bm);
    sum_parts<<<4, 256>>>();

    cudaFuncSetAttribute(gemm_kv, cudaFuncAttributeMaxDynamicSharedMemorySize, KV_SMEM);
    gemm_kv<<<dim3(8, 512), 256, KV_SMEM>>>();

    ln_lat_kernel<<<ROWS_L, 256>>>(lat, gl, bl);
    gemm_lat<<<dim3(24, 8), 256>>>(Wq, Wk, Wv, kvg);
    attn_kernel<<<dim3(SPLITS, H, Bb), 256>>>(mask);
    combine_kernel<<<512, 128>>>();
    gemm_out<<<dim3(16, 8), 256>>>(Wout, out);
}

// round 11
// speedup vs baseline: 3.2551x; 1.8251x over previous
#include <cuda_runtime.h>
#include <cuda_bf16.h>
#include <cstdint>
#include <cstddef>

#define DEV __device__ __forceinline__

namespace {
constexpr int Bb = 8, F = 8192, NL = 64, D = 1024, INNER = 512, H = 8, DH = 64;
constexpr int FN = F + NL;                 // 8256
constexpr int ROWS_X = Bb * F;             // 65536
constexpr int ROWS_L = Bb * NL;            // 512
constexpr int ROWS_KV = Bb * FN;           // 66048
constexpr float LN_EPS = 1e-5f;
constexpr float QSCALE = 0.125f;           // 64^-0.5
constexpr int SPLITS = 8;
constexpr int SPLEN = FN / SPLITS;         // 1032
constexpr int KV_SMEM = 2 * (4096 + 4096) * 4;   // 65536 B (2 stages x (A+B))
}

// ------------------- device scratch (static: no allocations allowed) -------------------
__device__ float g_mu[ROWS_X];
__device__ float g_rstd[ROWS_X];
__device__ float g_xr[(size_t)ROWS_X * D];        // tf32-rounded x
__device__ float g_latln[ROWS_L * D];
__device__ float g_bcatT[1024 * 1024];            // transposed gamma-folded [Wk|Wv]: [j][d], tf32-rounded
__device__ float g_partc[16 * 1024];
__device__ float g_partb[16 * 1024];
__device__ float g_csum[1024];
__device__ float g_bsum[1024];
__device__ float g_q[ROWS_L * INNER];
__device__ float g_k[(size_t)ROWS_KV * INNER];
__device__ float g_v[(size_t)ROWS_KV * INNER];
__device__ float g_y[ROWS_L * INNER];
__device__ float g_pm[Bb * H * SPLITS * NL];
__device__ float g_pl[Bb * H * SPLITS * NL];
__device__ float g_po[(size_t)Bb * H * SPLITS * NL * DH];

// ------------------- helpers -------------------
DEV unsigned f2tf(float x) {
    unsigned u;
    asm("cvt.rna.tf32.f32 %0, %1;" : "=r"(u) : "f"(x));
    return u;
}

DEV unsigned smem_u32(const void* p) {
    unsigned a;
    asm("{ .reg .u64 t; cvta.to.shared.u64 t, %1; cvt.u32.u64 %0, t; }" : "=r"(a) : "l"(p));
    return a;
}

DEV void cpa16(unsigned dst, const float* src) {
    asm volatile("cp.async.cg.shared.global [%0], [%1], 16;\n" :: "r"(dst), "l"(src) : "memory");
}

DEV void mma_tf32(float c[4], const unsigned a[4], const unsigned b[2]) {
    asm volatile(
        "mma.sync.aligned.m16n8k8.row.col.f32.tf32.tf32.f32 "
        "{%0,%1,%2,%3},{%4,%5,%6,%7},{%8,%9},{%0,%1,%2,%3};\n"
        : "+f"(c[0]), "+f"(c[1]), "+f"(c[2]), "+f"(c[3])
        : "r"(a[0]), "r"(a[1]), "r"(a[2]), "r"(a[3]), "r"(b[0]), "r"(b[1]));
}

// ------------------- 1) per-row mean / rstd of x + tf32-rounded copy -------------------
__global__ void __launch_bounds__(128) stats_x_kernel(const float* __restrict__ x) {
    int r = blockIdx.x;
    const float4* xr = (const float4*)(x + (size_t)r * D);
    int t = threadIdx.x;
    float4 a = xr[t];
    float4 b = xr[t + 128];
    float s  = a.x + a.y + a.z + a.w + b.x + b.y + b.z + b.w;
    float ss = a.x * a.x + a.y * a.y + a.z * a.z + a.w * a.w
             + b.x * b.x + b.y * b.y + b.z * b.z + b.w * b.w;
    float4 ra, rb;
    ra.x = __uint_as_float(f2tf(a.x)); ra.y = __uint_as_float(f2tf(a.y));
    ra.z = __uint_as_float(f2tf(a.z)); ra.w = __uint_as_float(f2tf(a.w));
    rb.x = __uint_as_float(f2tf(b.x)); rb.y = __uint_as_float(f2tf(b.y));
    rb.z = __uint_as_float(f2tf(b.z)); rb.w = __uint_as_float(f2tf(b.w));
    float4* xw = (float4*)(g_xr + (size_t)r * D);
    xw[t] = ra;
    xw[t + 128] = rb;
    #pragma unroll
    for (int o = 16; o; o >>= 1) {
        s  += __shfl_xor_sync(0xffffffffu, s, o);
        ss += __shfl_xor_sync(0xffffffffu, ss, o);
    }
    __shared__ float sh[8];
    int w = t >> 5;
    if ((t & 31) == 0) { sh[w] = s; sh[w + 4] = ss; }
    __syncthreads();
    if (t == 0) {
        s  = sh[0] + sh[1] + sh[2] + sh[3];
        ss = sh[4] + sh[5] + sh[6] + sh[7];
        float mu = s * (1.f / D);
        float var = ss * (1.f / D) - mu * mu;
        g_mu[r] = mu;
        g_rstd[r] = rsqrtf(var + LN_EPS);
    }
}

// ------------------- 2) latent layernorm -------------------
__global__ void __launch_bounds__(256) ln_lat_kernel(const float* __restrict__ lat,
                                                     const float* __restrict__ gl,
                                                     const float* __restrict__ bl) {
    int r = blockIdx.x;
    int t = threadIdx.x;
    const float4* xr = (const float4*)(lat + (size_t)r * D);
    float4 a = xr[t];
    float s  = a.x + a.y + a.z + a.w;
    float ss = a.x * a.x + a.y * a.y + a.z * a.z + a.w * a.w;
    #pragma unroll
    for (int o = 16; o; o >>= 1) {
        s  += __shfl_xor_sync(0xffffffffu, s, o);
        ss += __shfl_xor_sync(0xffffffffu, ss, o);
    }
    __shared__ float sh[18];
    int w = t >> 5;
    if ((t & 31) == 0) { sh[w] = s; sh[8 + w] = ss; }
    __syncthreads();
    if (t == 0) {
        s = 0.f; ss = 0.f;
        #pragma unroll
        for (int i = 0; i < 8; i++) { s += sh[i]; ss += sh[8 + i]; }
        float mu = s * (1.f / D);
        float var = ss * (1.f / D) - mu * mu;
        sh[16] = mu;
        sh[17] = rsqrtf(var + LN_EPS);
    }
    __syncthreads();
    float mu = sh[16], rs = sh[17];
    float4 g4 = ((const float4*)gl)[t];
    float4 b4 = ((const float4*)bl)[t];
    float4 o;
    o.x = (a.x - mu) * rs * g4.x + b4.x;
    o.y = (a.y - mu) * rs * g4.y + b4.y;
    o.z = (a.z - mu) * rs * g4.z + b4.z;
    o.w = (a.w - mu) * rs * g4.w + b4.w;
    ((float4*)(g_latln + (size_t)r * D))[t] = o;
}

// ------------------- 3) prep: transpose + gamma-fold (tf32) + partial colsums -------------------
__global__ void __launch_bounds__(256) prep_t(const float* __restrict__ Wk,
                                              const float* __restrict__ Wv,
                                              const float* __restrict__ gm,
                                              const float* __restrict__ bm) {
    __shared__ float sg[64][65];
    __shared__ float redc[4][64];
    __shared__ float redb[4][64];
    int t = threadIdx.x;
    int j0 = blockIdx.x * 64, d0 = blockIdx.y * 64;
    int jc = t & 63;
    int j = j0 + jc;
    const float* W = (j < 512) ? Wk : Wv;
    int jl = (j < 512) ? j : (j - 512);
    float pc = 0.f, pb = 0.f;
    #pragma unroll
    for (int i = 0; i < 16; i++) {
        int dr = (t >> 6) + i * 4;
        int d = d0 + dr;
        float w = W[(size_t)d * 512 + jl];
        float gv = __uint_as_float(f2tf(gm[d] * w));
        sg[dr][jc] = gv;
        pc += gv;
        pb += bm[d] * w;
    }
    redc[t >> 6][jc] = pc;
    redb[t >> 6][jc] = pb;
    __syncthreads();
    if (t < 64) {
        float c = redc[0][t] + redc[1][t] + redc[2][t] + redc[3][t];
        float b = redb[0][t] + redb[1][t] + redb[2][t] + redb[3][t];
        g_partc[blockIdx.y * 1024 + j0 + t] = c;
        g_partb[blockIdx.y * 1024 + j0 + t] = b;
    }
    #pragma unroll
    for (int i = 0; i < 16; i++) {
        int jr = (t >> 6) + i * 4;
        int dc = t & 63;
        g_bcatT[(size_t)(j0 + jr) * 1024 + d0 + dc] = sg[dc][jr];
    }
}

__global__ void __launch_bounds__(256) sum_parts() {
    int j = blockIdx.x * 256 + threadIdx.x;
    float c = 0.f, b = 0.f;
    #pragma unroll
    for (int i = 0; i < 16; i++) {
        c += g_partc[i * 1024 + j];
        b += g_partb[i * 1024 + j];
    }
    g_csum[j] = c;
    g_bsum[j] = b;
}

// ------------------- 4) big fused K/V GEMM: conflict-free swizzled smem + cp.async -------------------
DEV void kv_load_stage(unsigned sbase, int tid, int kt, int s, int m0, int n0) {
    int k0 = kt * 32;
    unsigned abase = sbase + (unsigned)s * 32768u;
    unsigned bbase = abase + 16384u;
    int row = tid >> 3;
    int atom = tid & 7;
    #pragma unroll
    for (int i = 0; i < 4; i++) {
        int r = row + i * 32;
        unsigned off = (unsigned)(r * 32 + ((atom ^ (r & 7)) << 2)) * 4u;
        cpa16(abase + off, g_xr + (size_t)(m0 + r) * 1024 + k0 + atom * 4);
        cpa16(bbase + off, g_bcatT + (size_t)(n0 + r) * 1024 + k0 + atom * 4);
    }
    asm volatile("cp.async.commit_group;\n" ::: "memory");
}

__global__ void __launch_bounds__(256) gemm_kv() {
    extern __shared__ unsigned sm[];
    unsigned sbase = smem_u32(sm);
    const int tid = threadIdx.x, warp = tid >> 5, lane = tid & 31;
    const int g = lane >> 2, tg = lane & 3;
    const int wm = warp >> 2, wn = warp & 3;
    const int m0 = blockIdx.y * 128, n0 = blockIdx.x * 128;

    float acc[4][4][4];
    #pragma unroll
    for (int a = 0; a < 4; a++)
        #pragma unroll
        for (int b = 0; b < 4; b++)
            #pragma unroll
            for (int c = 0; c < 4; c++) acc[a][b][c] = 0.f;

    kv_load_stage(sbase, tid, 0, 0, m0, n0);
    kv_load_stage(sbase, tid, 1, 1, m0, n0);

    for (int kt = 0; kt < 32; kt++) {
        const int s = kt & 1;
        if (kt < 31) asm volatile("cp.async.wait_group 1;\n" ::: "memory");
        else         asm volatile("cp.async.wait_group 0;\n" ::: "memory");
        __syncthreads();

        const unsigned* A_ = sm + s * 8192;
        const unsigned* B_ = A_ + 4096;
        #pragma unroll
        for (int ks = 0; ks < 4; ks++) {
            const int ks2 = ks * 2;
            const int x0 = ((ks2 ^ g) << 2) + tg;
            const int x1 = (((ks2 + 1) ^ g) << 2) + tg;
            unsigned af[4][4], bf[4][2];
            #pragma unroll
            for (int mf = 0; mf < 4; mf++) {
                const int r0 = (wm * 64 + mf * 16 + g) * 32;
                af[mf][0] = A_[r0 + x0];
                af[mf][1] = A_[r0 + 256 + x0];
                af[mf][2] = A_[r0 + x1];
                af[mf][3] = A_[r0 + 256 + x1];
            }
            #pragma unroll
            for (int nf = 0; nf < 4; nf++) {
                const int b0 = (wn * 32 + nf * 8 + g) * 32;
                bf[nf][0] = B_[b0 + x0];
                bf[nf][1] = B_[b0 + x1];
            }
            #pragma unroll
            for (int mf = 0; mf < 4; mf++)
                #pragma unroll
                for (int nf = 0; nf < 4; nf++)
                    mma_tf32(acc[mf][nf], af[mf], bf[nf]);
        }

        if (kt < 30) {
            __syncthreads();
            kv_load_stage(sbase, tid, kt + 2, s, m0, n0);
        }
    }

    #pragma unroll
    for (int mf = 0; mf < 4; mf++) {
        int r0 = m0 + wm * 64 + mf * 16 + g;
        int r1 = r0 + 8;
        float mu0 = g_mu[r0], rs0 = g_rstd[r0];
        float mu1 = g_mu[r1], rs1 = g_rstd[r1];
        size_t ro0 = (size_t)((r0 >> 13) * 8256 + (r0 & 8191));
        size_t ro1 = (size_t)((r1 >> 13) * 8256 + (r1 & 8191));
        #pragma unroll
        for (int nf = 0; nf < 4; nf++) {
            int c0 = n0 + wn * 32 + nf * 8 + 2 * tg;
            #pragma unroll
            for (int jj = 0; jj < 2; jj++) {
                int j = c0 + jj;
                float cs = g_csum[j], bs2 = g_bsum[j];
                float v0 = rs0 * (acc[mf][nf][jj] - mu0 * cs) + bs2;
                float v1 = rs1 * (acc[mf][nf][2 + jj] - mu1 * cs) + bs2;
                if (j < 512) {
                    g_k[ro0 * 512 + j] = v0;
                    g_k[ro1 * 512 + j] = v1;
                } else {
                    g_v[ro0 * 512 + (j - 512)] = v0;
                    g_v[ro1 * 512 + (j - 512)] = v1;
                }
            }
        }
    }
}

// ------------------- 5) latent Q/K/V GEMM (fp32 FFMA, small) -------------------
__global__ void __launch_bounds__(256) gemm_lat(const float* __restrict__ Wq,
                                                const float* __restrict__ Wk,
                                                const float* __restrict__ Wv,
                                                const float* __restrict__ kvg) {
    __shared__ float as_[64][17];
    __shared__ float bs_[16][65];
    int t = threadIdx.x;
    int n0 = blockIdx.x * 64, m0 = blockIdx.y * 64;
    int w = n0 >> 9;
    int nj0 = n0 & 511;
    const float* W = (w == 0) ? Wq : ((w == 1) ? Wk : Wv);
    int tx = t & 15, ty = t >> 4;
    float c[4][4] = {};
    for (int k0 = 0; k0 < 1024; k0 += 16) {
        #pragma unroll
        for (int i = 0; i < 4; i++) {
            int id = t + i * 256;
            as_[id >> 4][id & 15] = g_latln[(size_t)(m0 + (id >> 4)) * 1024 + k0 + (id & 15)];
        }
        #pragma unroll
        for (int i = 0; i < 4; i++) {
            int id = t + i * 256;
            bs_[id >> 6][id & 63] = W[(size_t)(k0 + (id >> 6)) * 512 + nj0 + (id & 63)];
        }
        __syncthreads();
        #pragma unroll
        for (int kk = 0; kk < 16; kk++) {
            float ra[4], rb[4];
            #pragma unroll
            for (int i = 0; i < 4; i++) ra[i] = as_[ty + 16 * i][kk];
            #pragma unroll
            for (int j = 0; j < 4; j++) rb[j] = bs_[kk][tx + 16 * j];
            #pragma unroll
            for (int i = 0; i < 4; i++)
                #pragma unroll
                for (int j = 0; j < 4; j++) c[i][j] += ra[i] * rb[j];
        }
        __syncthreads();
    }
    float gate = *kvg;
    #pragma unroll
    for (int i = 0; i < 4; i++)
        #pragma unroll
        for (int j = 0; j < 4; j++) {
            int m = m0 + ty + 16 * i;
            int J = n0 + tx + 16 * j;
            int b = m >> 6, li = m & 63;
            float v = c[i][j];
            if (w == 0) {
                g_q[(size_t)m * 512 + J] = v * QSCALE;
            } else if (w == 1) {
                g_k[((size_t)(b * 8256 + 8192 + li)) * 512 + (J - 512)] = v * gate;
            } else {
                g_v[((size_t)(b * 8256 + 8192 + li)) * 512 + (J - 1024)] = v * gate;
            }
        }
}

// ------------------- 6) split-KV flash attention on tensor cores (tf32 mma) -------------------
// Block = (split, head, batch); 128 threads / 4 warps; warp owns 16 q-rows x 64 cols.
__global__ void __launch_bounds__(128) attn_kernel(const int* __restrict__ mask) {
    __shared__ float ks_[64 * 68];   // K chunk [key][dh]; overlaid by per-warp P staging
    __shared__ float vs_[64 * 68];   // V chunk [key][dh]
    __shared__ float bias_[64];

    const int s = blockIdx.x, h = blockIdx.y, b = blockIdx.z;
    const int t = threadIdx.x;
    const int wid = t >> 5, lane = t & 31;
    const int g = lane >> 2, tg = lane & 3;
    const int r0 = wid * 16;
    const int base = s * SPLEN;

    // Q fragments (entire 16x64 warp tile) in registers, tf32-rounded
    unsigned qf[8][4];
    {
        const float* q0 = g_q + (size_t)(b * 64 + r0 + g) * 512 + h * 64;
        const float* q1 = q0 + 8 * 512;
        #pragma unroll
        for (int kk = 0; kk < 8; kk++) {
            qf[kk][0] = f2tf(q0[kk * 8 + tg]);
            qf[kk][1] = f2tf(q1[kk * 8 + tg]);
            qf[kk][2] = f2tf(q0[kk * 8 + tg + 4]);
            qf[kk][3] = f2tf(q1[kk * 8 + tg + 4]);
        }
    }

    float m0 = -1e30f, m1 = -1e30f, l0 = 0.f, l1 = 0.f;
    float oacc[8][4];
    #pragma unroll
    for (int nf = 0; nf < 8; nf++)
        #pragma unroll
        for (int i = 0; i < 4; i++) oacc[nf][i] = 0.f;

    for (int k0 = 0; k0 < 1088; k0 += 64) {      // 17 chunks of 64 (last padded via bias)
        __syncthreads();
        // load K/V chunk [64 keys][64 dh], tf32-rounded; rows clamped (bias masks them)
        #pragma unroll
        for (int i = 0; i < 8; i++) {
            int id = t + i * 128;
            int row = id >> 4, c4 = id & 15;
            int pos = base + k0 + row;
            int grow = b * 8256 + (pos < 8255 ? pos : 8255);
            size_t go = (size_t)grow * 512 + h * 64 + c4 * 4;
            float4 k4 = *reinterpret_cast<const float4*>(g_k + go);
            float4 v4 = *reinterpret_cast<const float4*>(g_v + go);
            float* kd = ks_ + row * 68 + c4 * 4;
            float* vd = vs_ + row * 68 + c4 * 4;
            kd[0] = __uint_as_float(f2tf(k4.x)); kd[1] = __uint_as_float(f2tf(k4.y));
            kd[2] = __uint_as_float(f2tf(k4.z)); kd[3] = __uint_as_float(f2tf(k4.w));
            vd[0] = __uint_as_float(f2tf(v4.x)); vd[1] = __uint_as_float(f2tf(v4.y));
            vd[2] = __uint_as_float(f2tf(v4.z)); vd[3] = __uint_as_float(f2tf(v4.w));
        }
        if (t < 64) {
            int pos = base + k0 + t;
            bool valid = (pos < base + SPLEN) && (pos >= F || mask[b * F + pos] == 0);
            bias_[t] = valid ? 0.f : -1e30f;
        }
        __syncthreads();

        // S = Q @ K^T  (warp tile 16x64)
        float sf[8][4];
        #pragma unroll
        for (int nf = 0; nf < 8; nf++)
            #pragma unroll
            for (int i = 0; i < 4; i++) sf[nf][i] = 0.f;
        #pragma unroll
        for (int kk = 0; kk < 8; kk++) {
            #pragma unroll
            for (int nf = 0; nf < 8; nf++) {
                unsigned bb[2];
                bb[0] = __float_as_uint(ks_[(nf * 8 + g) * 68 + kk * 8 + tg]);
                bb[1] = __float_as_uint(ks_[(nf * 8 + g) * 68 + kk * 8 + tg + 4]);
                mma_tf32(sf[nf], qf[kk], bb);
            }
        }

        // bias + online softmax (rows g and g+8; row spans 4 lanes -> shfl over tg bits)
        float cm0 = -1e30f, cm1 = -1e30f;
        #pragma unroll
        for (int nf = 0; nf < 8; nf++) {
            float b0 = bias_[nf * 8 + 2 * tg], b1 = bias_[nf * 8 + 2 * tg + 1];
            sf[nf][0] += b0; sf[nf][1] += b1; sf[nf][2] += b0; sf[nf][3] += b1;
            cm0 = fmaxf(cm0, fmaxf(sf[nf][0], sf[nf][1]));
            cm1 = fmaxf(cm1, fmaxf(sf[nf][2], sf[nf][3]));
        }
        cm0 = fmaxf(cm0, __shfl_xor_sync(0xffffffffu, cm0, 1));
        cm0 = fmaxf(cm0, __shfl_xor_sync(0xffffffffu, cm0, 2));
        cm1 = fmaxf(cm1, __shfl_xor_sync(0xffffffffu, cm1, 1));
        cm1 = fmaxf(cm1, __shfl_xor_sync(0xffffffffu, cm1, 2));
        float mn0 = fmaxf(m0, cm0), mn1 = fmaxf(m1, cm1);
        float sc0 = __expf(m0 - mn0), sc1 = __expf(m1 - mn1);
        m0 = mn0; m1 = mn1;
        float rs0 = 0.f, rs1 = 0.f;
        #pragma unroll
        for (int nf = 0; nf < 8; nf++) {
            sf[nf][0] = __expf(sf[nf][0] - mn0);
            sf[nf][1] = __expf(sf[nf][1] - mn0);
            sf[nf][2] = __expf(sf[nf][2] - mn1);
            sf[nf][3] = __expf(sf[nf][3] - mn1);
            rs0 += sf[nf][0] + sf[nf][1];
            rs1 += sf[nf][2] + sf[nf][3];
        }
        rs0 += __shfl_xor_sync(0xffffffffu, rs0, 1);
        rs0 += __shfl_xor_sync(0xffffffffu, rs0, 2);
        rs1 += __shfl_xor_sync(0xffffffffu, rs1, 1);
        rs1 += __shfl_xor_sync(0xffffffffu, rs1, 2);
        l0 = l0 * sc0 + rs0;
        l1 = l1 * sc1 + rs1;
        #pragma unroll
        for (int nf = 0; nf < 8; nf++) {
            oacc[nf][0] *= sc0; oacc[nf][1] *= sc0;
            oacc[nf][2] *= sc1; oacc[nf][3] *= sc1;
        }

        // stage P (tf32) into per-warp region overlaying ks_ (all warps done with K)
        __syncthreads();
        float* ps = ks_ + wid * (16 * 68);
        #pragma unroll
        for (int nf = 0; nf < 8; nf++) {
            float2 p0 = make_float2(__uint_as_float(f2tf(sf[nf][0])),
                                    __uint_as_float(f2tf(sf[nf][1])));
            float2 p1 = make_float2(__uint_as_float(f2tf(sf[nf][2])),
                                    __uint_as_float(f2tf(sf[nf][3])));
            *reinterpret_cast<float2*>(ps + g * 68 + nf * 8 + 2 * tg) = p0;
            *reinterpret_cast<float2*>(ps + (g + 8) * 68 + nf * 8 + 2 * tg) = p1;
        }
        __syncwarp();

        // O += P @ V
        #pragma unroll
        for (int kk = 0; kk < 8; kk++) {
            unsigned pa[4];
            pa[0] = __float_as_uint(ps[g * 68 + kk * 8 + tg]);
            pa[1] = __float_as_uint(ps[(g + 8) * 68 + kk * 8 + tg]);
            pa[2] = __float_as_uint(ps[g * 68 + kk * 8 + tg + 4]);
            pa[3] = __float_as_uint(ps[(g + 8) * 68 + kk * 8 + tg + 4]);
            #pragma unroll
            for (int nf = 0; nf < 8; nf++) {
                unsigned bb[2];
                bb[0] = __float_as_uint(vs_[(kk * 8 + tg) * 68 + nf * 8 + g]);
                bb[1] = __float_as_uint(vs_[(kk * 8 + tg + 4) * 68 + nf * 8 + g]);
                mma_tf32(oacc[nf], pa, bb);
            }
        }
    }

    // write split partials (same layout as combine expects)
    int idx0 = ((b * 8 + h) * 8 + s) * 64 + r0 + g;
    int idx1 = idx0 + 8;
    if (tg == 0) {
        g_pm[idx0] = m0; g_pl[idx0] = l0;
        g_pm[idx1] = m1; g_pl[idx1] = l1;
    }
    #pragma unroll
    for (int nf = 0; nf < 8; nf++) {
        *reinterpret_cast<float2*>(g_po + (size_t)idx0 * 64 + nf * 8 + 2 * tg) =
            make_float2(oacc[nf][0], oacc[nf][1]);
        *reinterpret_cast<float2*>(g_po + (size_t)idx1 * 64 + nf * 8 + 2 * tg) =
            make_float2(oacc[nf][2], oacc[nf][3]);
    }
}

// ------------------- 7) split combine -> y -------------------
__global__ void __launch_bounds__(128) combine_kernel() {
    int bq = blockIdx.x;
    int b = bq >> 6, qr = bq & 63;
    int t = threadIdx.x;
    int h = t >> 4, c0 = (t & 15) * 4;
    int idx0 = ((b * 8 + h) * 8) * 64 + qr;
    float M = -1e30f;
    #pragma unroll
    for (int s = 0; s < SPLITS; s++) M = fmaxf(M, g_pm[idx0 + s * 64]);
    float L = 0.f;
    float a[4] = {0.f, 0.f, 0.f, 0.f};
    #pragma unroll
    for (int s = 0; s < SPLITS; s++) {
        float w = __expf(g_pm[idx0 + s * 64] - M);
        L += g_pl[idx0 + s * 64] * w;
        size_t pb = (size_t)(idx0 + s * 64) * 64 + c0;
        #pragma unroll
        for (int j = 0; j < 4; j++) a[j] += g_po[pb + j] * w;
    }
    float inv = 1.f / L;
    size_t yo = (size_t)(b * 64 + qr) * 512 + h * 64 + c0;
    #pragma unroll
    for (int j = 0; j < 4; j++) g_y[yo + j] = a[j] * inv;
}

// ------------------- 8) output projection: out = y @ Wout -------------------
__global__ void __launch_bounds__(256) gemm_out(const float* __restrict__ Wout,
                                                float* __restrict__ out) {
    __shared__ float as_[64][17];
    __shared__ float bs_[16][65];
    int t = threadIdx.x;
    int n0 = blockIdx.x * 64, m0 = blockIdx.y * 64;
    int tx = t & 15, ty = t >> 4;
    float c[4][4] = {};
    for (int k0 = 0; k0 < 512; k0 += 16) {
        #pragma unroll
        for (int i = 0; i < 4; i++) {
            int id = t + i * 256;
            as_[id >> 4][id & 15] = g_y[(size_t)(m0 + (id >> 4)) * 512 + k0 + (id & 15)];
        }
        #pragma unroll
        for (int i = 0; i < 4; i++) {
            int id = t + i * 256;
            bs_[id >> 6][id & 63] = Wout[(size_t)(k0 + (id >> 6)) * 1024 + n0 + (id & 63)];
        }
        __syncthreads();
        #pragma unroll
        for (int kk = 0; kk < 16; kk++) {
            float ra[4], rb[4];
            #pragma unroll
            for (int i = 0; i < 4; i++) ra[i] = as_[ty + 16 * i][kk];
            #pragma unroll
            for (int j = 0; j < 4; j++) rb[j] = bs_[kk][tx + 16 * j];
            #pragma unroll
            for (int i = 0; i < 4; i++)
                #pragma unroll
                for (int j = 0; j < 4; j++) c[i][j] += ra[i] * rb[j];
        }
        __syncthreads();
    }
    #pragma unroll
    for (int i = 0; i < 4; i++)
        #pragma unroll
        for (int j = 0; j < 4; j++)
            out[(size_t)(m0 + ty + 16 * i) * 1024 + n0 + tx + 16 * j] = c[i][j];
}

// ------------------- launch -------------------
extern "C" void kernel_launch(void* const* d_in, const int* in_sizes, int n_in,
                              void* d_out, int out_size) {
    (void)in_sizes; (void)n_in; (void)out_size;
    const float* x   = (const float*)d_in[0];
    const float* lat = (const float*)d_in[1];
    const int*   mask = (const int*)d_in[2];          // bool -> int32 per harness contract
    const float* kvg = (const float*)d_in[3];
    const float* gm  = (const float*)d_in[4];
    const float* bm  = (const float*)d_in[5];
    const float* gl  = (const float*)d_in[6];
    const float* bl  = (const float*)d_in[7];
    const float* Wq  = (const float*)d_in[8];
    const float* Wk  = (const float*)d_in[9];
    const float* Wv  = (const float*)d_in[10];
    const float* Wout = (const float*)d_in[11];
    float* out = (float*)d_out;

    stats_x_kernel<<<ROWS_X, 128>>>(x);
    prep_t<<<dim3(16, 16), 256>>>(Wk, Wv, gm, bm);
    sum_parts<<<4, 256>>>();

    cudaFuncSetAttribute(gemm_kv, cudaFuncAttributeMaxDynamicSharedMemorySize, KV_SMEM);
    gemm_kv<<<dim3(8, 512), 256, KV_SMEM>>>();

    ln_lat_kernel<<<ROWS_L, 256>>>(lat, gl, bl);
    gemm_lat<<<dim3(24, 8), 256>>>(Wq, Wk, Wv, kvg);
    attn_kernel<<<dim3(SPLITS, H, Bb), 128>>>(mask);
    combine_kernel<<<512, 128>>>();
    gemm_out<<<dim3(16, 8), 256>>>(Wout, out);
}

// round 12
// speedup vs baseline: 3.4602x; 1.0630x over previous
#include <cuda_runtime.h>
#include <cuda_bf16.h>
#include <cstdint>
#include <cstddef>

#define DEV __device__ __forceinline__

namespace {
constexpr int Bb = 8, F = 8192, NL = 64, D = 1024, INNER = 512, H = 8, DH = 64;
constexpr int FN = F + NL;                 // 8256
constexpr int ROWS_X = Bb * F;             // 65536
constexpr int ROWS_L = Bb * NL;            // 512
constexpr int ROWS_KV = Bb * FN;           // 66048
constexpr float LN_EPS = 1e-5f;
constexpr float QSCALE = 0.125f;           // 64^-0.5
constexpr int SPLITS = 8;
constexpr int SPLEN = FN / SPLITS;         // 1032
constexpr int KV_SMEM = 2 * (4096 + 4096) * 4;   // 65536 B (2 stages x (A+B))
}

// ------------------- device scratch (static: no allocations allowed) -------------------
__device__ float g_mu[ROWS_X];
__device__ float g_rstd[ROWS_X];
__device__ float g_xr[(size_t)ROWS_X * D];        // tf32-rounded x
__device__ float g_latln[ROWS_L * D];
__device__ float g_bcatT[1024 * 1024];            // transposed gamma-folded [Wk|Wv]: [j][d], tf32-rounded
__device__ float g_partc[16 * 1024];
__device__ float g_partb[16 * 1024];
__device__ float g_csum[1024];
__device__ float g_bsum[1024];
__device__ float g_q[ROWS_L * INNER];
__device__ float g_k[(size_t)ROWS_KV * INNER];
__device__ float g_v[(size_t)ROWS_KV * INNER];
__device__ float g_y[ROWS_L * INNER];
__device__ float g_pm[Bb * H * SPLITS * NL];
__device__ float g_pl[Bb * H * SPLITS * NL];
__device__ float g_po[(size_t)Bb * H * SPLITS * NL * DH];

// ------------------- helpers -------------------
DEV unsigned f2tf(float x) {
    unsigned u;
    asm("cvt.rna.tf32.f32 %0, %1;" : "=r"(u) : "f"(x));
    return u;
}

DEV unsigned smem_u32(const void* p) {
    unsigned a;
    asm("{ .reg .u64 t; cvta.to.shared.u64 t, %1; cvt.u32.u64 %0, t; }" : "=r"(a) : "l"(p));
    return a;
}

DEV void cpa16(unsigned dst, const float* src) {
    asm volatile("cp.async.cg.shared.global [%0], [%1], 16;\n" :: "r"(dst), "l"(src) : "memory");
}

DEV void mma_tf32(float c[4], const unsigned a[4], const unsigned b[2]) {
    asm volatile(
        "mma.sync.aligned.m16n8k8.row.col.f32.tf32.tf32.f32 "
        "{%0,%1,%2,%3},{%4,%5,%6,%7},{%8,%9},{%0,%1,%2,%3};\n"
        : "+f"(c[0]), "+f"(c[1]), "+f"(c[2]), "+f"(c[3])
        : "r"(a[0]), "r"(a[1]), "r"(a[2]), "r"(a[3]), "r"(b[0]), "r"(b[1]));
}

DEV void ldsm4(unsigned& r0, unsigned& r1, unsigned& r2, unsigned& r3, unsigned a) {
    asm volatile("ldmatrix.sync.aligned.m8n8.x4.shared.b16 {%0,%1,%2,%3}, [%4];"
                 : "=r"(r0), "=r"(r1), "=r"(r2), "=r"(r3) : "r"(a));
}

// ------------------- 1) per-row mean / rstd of x + tf32-rounded copy -------------------
__global__ void __launch_bounds__(128) stats_x_kernel(const float* __restrict__ x) {
    int r = blockIdx.x;
    const float4* xr = (const float4*)(x + (size_t)r * D);
    int t = threadIdx.x;
    float4 a = xr[t];
    float4 b = xr[t + 128];
    float s  = a.x + a.y + a.z + a.w + b.x + b.y + b.z + b.w;
    float ss = a.x * a.x + a.y * a.y + a.z * a.z + a.w * a.w
             + b.x * b.x + b.y * b.y + b.z * b.z + b.w * b.w;
    float4 ra, rb;
    ra.x = __uint_as_float(f2tf(a.x)); ra.y = __uint_as_float(f2tf(a.y));
    ra.z = __uint_as_float(f2tf(a.z)); ra.w = __uint_as_float(f2tf(a.w));
    rb.x = __uint_as_float(f2tf(b.x)); rb.y = __uint_as_float(f2tf(b.y));
    rb.z = __uint_as_float(f2tf(b.z)); rb.w = __uint_as_float(f2tf(b.w));
    float4* xw = (float4*)(g_xr + (size_t)r * D);
    xw[t] = ra;
    xw[t + 128] = rb;
    #pragma unroll
    for (int o = 16; o; o >>= 1) {
        s  += __shfl_xor_sync(0xffffffffu, s, o);
        ss += __shfl_xor_sync(0xffffffffu, ss, o);
    }
    __shared__ float sh[8];
    int w = t >> 5;
    if ((t & 31) == 0) { sh[w] = s; sh[w + 4] = ss; }
    __syncthreads();
    if (t == 0) {
        s  = sh[0] + sh[1] + sh[2] + sh[3];
        ss = sh[4] + sh[5] + sh[6] + sh[7];
        float mu = s * (1.f / D);
        float var = ss * (1.f / D) - mu * mu;
        g_mu[r] = mu;
        g_rstd[r] = rsqrtf(var + LN_EPS);
    }
}

// ------------------- 2) latent layernorm -------------------
__global__ void __launch_bounds__(256) ln_lat_kernel(const float* __restrict__ lat,
                                                     const float* __restrict__ gl,
                                                     const float* __restrict__ bl) {
    int r = blockIdx.x;
    int t = threadIdx.x;
    const float4* xr = (const float4*)(lat + (size_t)r * D);
    float4 a = xr[t];
    float s  = a.x + a.y + a.z + a.w;
    float ss = a.x * a.x + a.y * a.y + a.z * a.z + a.w * a.w;
    #pragma unroll
    for (int o = 16; o; o >>= 1) {
        s  += __shfl_xor_sync(0xffffffffu, s, o);
        ss += __shfl_xor_sync(0xffffffffu, ss, o);
    }
    __shared__ float sh[18];
    int w = t >> 5;
    if ((t & 31) == 0) { sh[w] = s; sh[8 + w] = ss; }
    __syncthreads();
    if (t == 0) {
        s = 0.f; ss = 0.f;
        #pragma unroll
        for (int i = 0; i < 8; i++) { s += sh[i]; ss += sh[8 + i]; }
        float mu = s * (1.f / D);
        float var = ss * (1.f / D) - mu * mu;
        sh[16] = mu;
        sh[17] = rsqrtf(var + LN_EPS);
    }
    __syncthreads();
    float mu = sh[16], rs = sh[17];
    float4 g4 = ((const float4*)gl)[t];
    float4 b4 = ((const float4*)bl)[t];
    float4 o;
    o.x = (a.x - mu) * rs * g4.x + b4.x;
    o.y = (a.y - mu) * rs * g4.y + b4.y;
    o.z = (a.z - mu) * rs * g4.z + b4.z;
    o.w = (a.w - mu) * rs * g4.w + b4.w;
    ((float4*)(g_latln + (size_t)r * D))[t] = o;
}

// ------------------- 3) prep: transpose + gamma-fold (tf32) + partial colsums -------------------
__global__ void __launch_bounds__(256) prep_t(const float* __restrict__ Wk,
                                              const float* __restrict__ Wv,
                                              const float* __restrict__ gm,
                                              const float* __restrict__ bm) {
    __shared__ float sg[64][65];
    __shared__ float redc[4][64];
    __shared__ float redb[4][64];
    int t = threadIdx.x;
    int j0 = blockIdx.x * 64, d0 = blockIdx.y * 64;
    int jc = t & 63;
    int j = j0 + jc;
    const float* W = (j < 512) ? Wk : Wv;
    int jl = (j < 512) ? j : (j - 512);
    float pc = 0.f, pb = 0.f;
    #pragma unroll
    for (int i = 0; i < 16; i++) {
        int dr = (t >> 6) + i * 4;
        int d = d0 + dr;
        float w = W[(size_t)d * 512 + jl];
        float gv = __uint_as_float(f2tf(gm[d] * w));
        sg[dr][jc] = gv;
        pc += gv;
        pb += bm[d] * w;
    }
    redc[t >> 6][jc] = pc;
    redb[t >> 6][jc] = pb;
    __syncthreads();
    if (t < 64) {
        float c = redc[0][t] + redc[1][t] + redc[2][t] + redc[3][t];
        float b = redb[0][t] + redb[1][t] + redb[2][t] + redb[3][t];
        g_partc[blockIdx.y * 1024 + j0 + t] = c;
        g_partb[blockIdx.y * 1024 + j0 + t] = b;
    }
    #pragma unroll
    for (int i = 0; i < 16; i++) {
        int jr = (t >> 6) + i * 4;
        int dc = t & 63;
        g_bcatT[(size_t)(j0 + jr) * 1024 + d0 + dc] = sg[dc][jr];
    }
}

__global__ void __launch_bounds__(256) sum_parts() {
    int j = blockIdx.x * 256 + threadIdx.x;
    float c = 0.f, b = 0.f;
    #pragma unroll
    for (int i = 0; i < 16; i++) {
        c += g_partc[i * 1024 + j];
        b += g_partb[i * 1024 + j];
    }
    g_csum[j] = c;
    g_bsum[j] = b;
}

// ------------------- 4) big fused K/V GEMM: swizzled smem + cp.async + ldmatrix -------------------
DEV void kv_load_stage(unsigned sbase, int tid, int kt, int s, int m0, int n0) {
    int k0 = kt * 32;
    unsigned abase = sbase + (unsigned)s * 32768u;
    unsigned bbase = abase + 16384u;
    int row = tid >> 3;
    int atom = tid & 7;
    #pragma unroll
    for (int i = 0; i < 4; i++) {
        int r = row + i * 32;
        unsigned off = (unsigned)(r * 32 + ((atom ^ (r & 7)) << 2)) * 4u;
        cpa16(abase + off, g_xr + (size_t)(m0 + r) * 1024 + k0 + atom * 4);
        cpa16(bbase + off, g_bcatT + (size_t)(n0 + r) * 1024 + k0 + atom * 4);
    }
    asm volatile("cp.async.commit_group;\n" ::: "memory");
}

__global__ void __launch_bounds__(256) gemm_kv() {
    extern __shared__ unsigned sm[];
    unsigned sbase = smem_u32(sm);
    const int tid = threadIdx.x, warp = tid >> 5, lane = tid & 31;
    const int g = lane >> 2, tg = lane & 3;
    const int wm = warp >> 2, wn = warp & 3;
    const int m0 = blockIdx.y * 128, n0 = blockIdx.x * 128;

    // ldmatrix per-lane invariants
    const unsigned i7 = lane & 7;
    const unsigned mh = (lane >> 3) & 1;   // matrix row-half selector
    const unsigned ms = lane >> 4;         // matrix pair selector
    const unsigned rowA = (unsigned)(wm * 64) + i7 + mh * 8;      // + mf*16
    const unsigned rowB = (unsigned)(wn * 32) + ms * 8 + i7;      // + p*16

    float acc[4][4][4];
    #pragma unroll
    for (int a = 0; a < 4; a++)
        #pragma unroll
        for (int b = 0; b < 4; b++)
            #pragma unroll
            for (int c = 0; c < 4; c++) acc[a][b][c] = 0.f;

    kv_load_stage(sbase, tid, 0, 0, m0, n0);
    kv_load_stage(sbase, tid, 1, 1, m0, n0);

    for (int kt = 0; kt < 32; kt++) {
        const int s = kt & 1;
        if (kt < 31) asm volatile("cp.async.wait_group 1;\n" ::: "memory");
        else         asm volatile("cp.async.wait_group 0;\n" ::: "memory");
        __syncthreads();

        const unsigned Ab = sbase + (unsigned)s * 32768u;
        const unsigned Bbs = Ab + 16384u;
        #pragma unroll
        for (int ks = 0; ks < 4; ks++) {
            unsigned af[4][4], bf[4][2];
            const unsigned aAtom = (unsigned)(2 * ks) + ms;       // A: matrix pair -> k-atom
            const unsigned bAtom = (unsigned)(2 * ks) + mh;       // B: row-half -> k-atom
            #pragma unroll
            for (int mf = 0; mf < 4; mf++) {
                unsigned ad = Ab + ((rowA + mf * 16) * 32 + ((aAtom ^ i7) << 2)) * 4u;
                ldsm4(af[mf][0], af[mf][1], af[mf][2], af[mf][3], ad);
            }
            #pragma unroll
            for (int p = 0; p < 2; p++) {
                unsigned bd = Bbs + ((rowB + p * 16) * 32 + ((bAtom ^ i7) << 2)) * 4u;
                ldsm4(bf[2 * p][0], bf[2 * p][1], bf[2 * p + 1][0], bf[2 * p + 1][1], bd);
            }
            #pragma unroll
            for (int mf = 0; mf < 4; mf++)
                #pragma unroll
                for (int nf = 0; nf < 4; nf++)
                    mma_tf32(acc[mf][nf], af[mf], bf[nf]);
        }

        if (kt < 30) {
            __syncthreads();
            kv_load_stage(sbase, tid, kt + 2, s, m0, n0);
        }
    }

    #pragma unroll
    for (int mf = 0; mf < 4; mf++) {
        int r0 = m0 + wm * 64 + mf * 16 + g;
        int r1 = r0 + 8;
        float mu0 = g_mu[r0], rs0 = g_rstd[r0];
        float mu1 = g_mu[r1], rs1 = g_rstd[r1];
        size_t ro0 = (size_t)((r0 >> 13) * 8256 + (r0 & 8191));
        size_t ro1 = (size_t)((r1 >> 13) * 8256 + (r1 & 8191));
        #pragma unroll
        for (int nf = 0; nf < 4; nf++) {
            int c0 = n0 + wn * 32 + nf * 8 + 2 * tg;
            #pragma unroll
            for (int jj = 0; jj < 2; jj++) {
                int j = c0 + jj;
                float cs = g_csum[j], bs2 = g_bsum[j];
                float v0 = rs0 * (acc[mf][nf][jj] - mu0 * cs) + bs2;
                float v1 = rs1 * (acc[mf][nf][2 + jj] - mu1 * cs) + bs2;
                if (j < 512) {
                    g_k[ro0 * 512 + j] = v0;
                    g_k[ro1 * 512 + j] = v1;
                } else {
                    g_v[ro0 * 512 + (j - 512)] = v0;
                    g_v[ro1 * 512 + (j - 512)] = v1;
                }
            }
        }
    }
}

// ------------------- 5) latent Q/K/V GEMM (fp32 FFMA, small) -------------------
__global__ void __launch_bounds__(256) gemm_lat(const float* __restrict__ Wq,
                                                const float* __restrict__ Wk,
                                                const float* __restrict__ Wv,
                                                const float* __restrict__ kvg) {
    __shared__ float as_[64][17];
    __shared__ float bs_[16][65];
    int t = threadIdx.x;
    int n0 = blockIdx.x * 64, m0 = blockIdx.y * 64;
    int w = n0 >> 9;
    int nj0 = n0 & 511;
    const float* W = (w == 0) ? Wq : ((w == 1) ? Wk : Wv);
    int tx = t & 15, ty = t >> 4;
    float c[4][4] = {};
    for (int k0 = 0; k0 < 1024; k0 += 16) {
        #pragma unroll
        for (int i = 0; i < 4; i++) {
            int id = t + i * 256;
            as_[id >> 4][id & 15] = g_latln[(size_t)(m0 + (id >> 4)) * 1024 + k0 + (id & 15)];
        }
        #pragma unroll
        for (int i = 0; i < 4; i++) {
            int id = t + i * 256;
            bs_[id >> 6][id & 63] = W[(size_t)(k0 + (id >> 6)) * 512 + nj0 + (id & 63)];
        }
        __syncthreads();
        #pragma unroll
        for (int kk = 0; kk < 16; kk++) {
            float ra[4], rb[4];
            #pragma unroll
            for (int i = 0; i < 4; i++) ra[i] = as_[ty + 16 * i][kk];
            #pragma unroll
            for (int j = 0; j < 4; j++) rb[j] = bs_[kk][tx + 16 * j];
            #pragma unroll
            for (int i = 0; i < 4; i++)
                #pragma unroll
                for (int j = 0; j < 4; j++) c[i][j] += ra[i] * rb[j];
        }
        __syncthreads();
    }
    float gate = *kvg;
    #pragma unroll
    for (int i = 0; i < 4; i++)
        #pragma unroll
        for (int j = 0; j < 4; j++) {
            int m = m0 + ty + 16 * i;
            int J = n0 + tx + 16 * j;
            int b = m >> 6, li = m & 63;
            float v = c[i][j];
            if (w == 0) {
                g_q[(size_t)m * 512 + J] = v * QSCALE;
            } else if (w == 1) {
                g_k[((size_t)(b * 8256 + 8192 + li)) * 512 + (J - 512)] = v * gate;
            } else {
                g_v[((size_t)(b * 8256 + 8192 + li)) * 512 + (J - 1024)] = v * gate;
            }
        }
}

// ------------------- 6) split-KV flash attention on tensor cores (tf32 mma) -------------------
__global__ void __launch_bounds__(128) attn_kernel(const int* __restrict__ mask) {
    __shared__ float ks_[64 * 68];   // K chunk [key][dh]; overlaid by per-warp P staging
    __shared__ float vs_[64 * 68];   // V chunk [key][dh]
    __shared__ float bias_[64];

    const int s = blockIdx.x, h = blockIdx.y, b = blockIdx.z;
    const int t = threadIdx.x;
    const int wid = t >> 5, lane = t & 31;
    const int g = lane >> 2, tg = lane & 3;
    const int r0 = wid * 16;
    const int base = s * SPLEN;

    unsigned qf[8][4];
    {
        const float* q0 = g_q + (size_t)(b * 64 + r0 + g) * 512 + h * 64;
        const float* q1 = q0 + 8 * 512;
        #pragma unroll
        for (int kk = 0; kk < 8; kk++) {
            qf[kk][0] = f2tf(q0[kk * 8 + tg]);
            qf[kk][1] = f2tf(q1[kk * 8 + tg]);
            qf[kk][2] = f2tf(q0[kk * 8 + tg + 4]);
            qf[kk][3] = f2tf(q1[kk * 8 + tg + 4]);
        }
    }

    float m0 = -1e30f, m1 = -1e30f, l0 = 0.f, l1 = 0.f;
    float oacc[8][4];
    #pragma unroll
    for (int nf = 0; nf < 8; nf++)
        #pragma unroll
        for (int i = 0; i < 4; i++) oacc[nf][i] = 0.f;

    for (int k0 = 0; k0 < 1088; k0 += 64) {
        __syncthreads();
        #pragma unroll
        for (int i = 0; i < 8; i++) {
            int id = t + i * 128;
            int row = id >> 4, c4 = id & 15;
            int pos = base + k0 + row;
            int grow = b * 8256 + (pos < 8255 ? pos : 8255);
            size_t go = (size_t)grow * 512 + h * 64 + c4 * 4;
            float4 k4 = *reinterpret_cast<const float4*>(g_k + go);
            float4 v4 = *reinterpret_cast<const float4*>(g_v + go);
            float* kd = ks_ + row * 68 + c4 * 4;
            float* vd = vs_ + row * 68 + c4 * 4;
            kd[0] = __uint_as_float(f2tf(k4.x)); kd[1] = __uint_as_float(f2tf(k4.y));
            kd[2] = __uint_as_float(f2tf(k4.z)); kd[3] = __uint_as_float(f2tf(k4.w));
            vd[0] = __uint_as_float(f2tf(v4.x)); vd[1] = __uint_as_float(f2tf(v4.y));
            vd[2] = __uint_as_float(f2tf(v4.z)); vd[3] = __uint_as_float(f2tf(v4.w));
        }
        if (t < 64) {
            int pos = base + k0 + t;
            bool valid = (pos < base + SPLEN) && (pos >= F || mask[b * F + pos] == 0);
            bias_[t] = valid ? 0.f : -1e30f;
        }
        __syncthreads();

        float sf[8][4];
        #pragma unroll
        for (int nf = 0; nf < 8; nf++)
            #pragma unroll
            for (int i = 0; i < 4; i++) sf[nf][i] = 0.f;
        #pragma unroll
        for (int kk = 0; kk < 8; kk++) {
            #pragma unroll
            for (int nf = 0; nf < 8; nf++) {
                unsigned bb[2];
                bb[0] = __float_as_uint(ks_[(nf * 8 + g) * 68 + kk * 8 + tg]);
                bb[1] = __float_as_uint(ks_[(nf * 8 + g) * 68 + kk * 8 + tg + 4]);
                mma_tf32(sf[nf], qf[kk], bb);
            }
        }

        float cm0 = -1e30f, cm1 = -1e30f;
        #pragma unroll
        for (int nf = 0; nf < 8; nf++) {
            float b0 = bias_[nf * 8 + 2 * tg], b1 = bias_[nf * 8 + 2 * tg + 1];
            sf[nf][0] += b0; sf[nf][1] += b1; sf[nf][2] += b0; sf[nf][3] += b1;
            cm0 = fmaxf(cm0, fmaxf(sf[nf][0], sf[nf][1]));
            cm1 = fmaxf(cm1, fmaxf(sf[nf][2], sf[nf][3]));
        }
        cm0 = fmaxf(cm0, __shfl_xor_sync(0xffffffffu, cm0, 1));
        cm0 = fmaxf(cm0, __shfl_xor_sync(0xffffffffu, cm0, 2));
        cm1 = fmaxf(cm1, __shfl_xor_sync(0xffffffffu, cm1, 1));
        cm1 = fmaxf(cm1, __shfl_xor_sync(0xffffffffu, cm1, 2));
        float mn0 = fmaxf(m0, cm0), mn1 = fmaxf(m1, cm1);
        float sc0 = __expf(m0 - mn0), sc1 = __expf(m1 - mn1);
        m0 = mn0; m1 = mn1;
        float rs0 = 0.f, rs1 = 0.f;
        #pragma unroll
        for (int nf = 0; nf < 8; nf++) {
            sf[nf][0] = __expf(sf[nf][0] - mn0);
            sf[nf][1] = __expf(sf[nf][1] - mn0);
            sf[nf][2] = __expf(sf[nf][2] - mn1);
            sf[nf][3] = __expf(sf[nf][3] - mn1);
            rs0 += sf[nf][0] + sf[nf][1];
            rs1 += sf[nf][2] + sf[nf][3];
        }
        rs0 += __shfl_xor_sync(0xffffffffu, rs0, 1);
        rs0 += __shfl_xor_sync(0xffffffffu, rs0, 2);
        rs1 += __shfl_xor_sync(0xffffffffu, rs1, 1);
        rs1 += __shfl_xor_sync(0xffffffffu, rs1, 2);
        l0 = l0 * sc0 + rs0;
        l1 = l1 * sc1 + rs1;
        #pragma unroll
        for (int nf = 0; nf < 8; nf++) {
            oacc[nf][0] *= sc0; oacc[nf][1] *= sc0;
            oacc[nf][2] *= sc1; oacc[nf][3] *= sc1;
        }

        __syncthreads();
        float* ps = ks_ + wid * (16 * 68);
        #pragma unroll
        for (int nf = 0; nf < 8; nf++) {
            float2 p0 = make_float2(__uint_as_float(f2tf(sf[nf][0])),
                                    __uint_as_float(f2tf(sf[nf][1])));
            float2 p1 = make_float2(__uint_as_float(f2tf(sf[nf][2])),
                                    __uint_as_float(f2tf(sf[nf][3])));
            *reinterpret_cast<float2*>(ps + g * 68 + nf * 8 + 2 * tg) = p0;
            *reinterpret_cast<float2*>(ps + (g + 8) * 68 + nf * 8 + 2 * tg) = p1;
        }
        __syncwarp();

        #pragma unroll
        for (int kk = 0; kk < 8; kk++) {
            unsigned pa[4];
            pa[0] = __float_as_uint(ps[g * 68 + kk * 8 + tg]);
            pa[1] = __float_as_uint(ps[(g + 8) * 68 + kk * 8 + tg]);
            pa[2] = __float_as_uint(ps[g * 68 + kk * 8 + tg + 4]);
            pa[3] = __float_as_uint(ps[(g + 8) * 68 + kk * 8 + tg + 4]);
            #pragma unroll
            for (int nf = 0; nf < 8; nf++) {
                unsigned bb[2];
                bb[0] = __float_as_uint(vs_[(kk * 8 + tg) * 68 + nf * 8 + g]);
                bb[1] = __float_as_uint(vs_[(kk * 8 + tg + 4) * 68 + nf * 8 + g]);
                mma_tf32(oacc[nf], pa, bb);
            }
        }
    }

    int idx0 = ((b * 8 + h) * 8 + s) * 64 + r0 + g;
    int idx1 = idx0 + 8;
    if (tg == 0) {
        g_pm[idx0] = m0; g_pl[idx0] = l0;
        g_pm[idx1] = m1; g_pl[idx1] = l1;
    }
    #pragma unroll
    for (int nf = 0; nf < 8; nf++) {
        *reinterpret_cast<float2*>(g_po + (size_t)idx0 * 64 + nf * 8 + 2 * tg) =
            make_float2(oacc[nf][0], oacc[nf][1]);
        *reinterpret_cast<float2*>(g_po + (size_t)idx1 * 64 + nf * 8 + 2 * tg) =
            make_float2(oacc[nf][2], oacc[nf][3]);
    }
}

// ------------------- 7) split combine -> y -------------------
__global__ void __launch_bounds__(128) combine_kernel() {
    int bq = blockIdx.x;
    int b = bq >> 6, qr = bq & 63;
    int t = threadIdx.x;
    int h = t >> 4, c0 = (t & 15) * 4;
    int idx0 = ((b * 8 + h) * 8) * 64 + qr;
    float M = -1e30f;
    #pragma unroll
    for (int s = 0; s < SPLITS; s++) M = fmaxf(M, g_pm[idx0 + s * 64]);
    float L = 0.f;
    float a[4] = {0.f, 0.f, 0.f, 0.f};
    #pragma unroll
    for (int s = 0; s < SPLITS; s++) {
        float w = __expf(g_pm[idx0 + s * 64] - M);
        L += g_pl[idx0 + s * 64] * w;
        size_t pb = (size_t)(idx0 + s * 64) * 64 + c0;
        #pragma unroll
        for (int j = 0; j < 4; j++) a[j] += g_po[pb + j] * w;
    }
    float inv = 1.f / L;
    size_t yo = (size_t)(b * 64 + qr) * 512 + h * 64 + c0;
    #pragma unroll
    for (int j = 0; j < 4; j++) g_y[yo + j] = a[j] * inv;
}

// ------------------- 8) output projection: out = y @ Wout -------------------
__global__ void __launch_bounds__(256) gemm_out(const float* __restrict__ Wout,
                                                float* __restrict__ out) {
    __shared__ float as_[64][17];
    __shared__ float bs_[16][65];
    int t = threadIdx.x;
    int n0 = blockIdx.x * 64, m0 = blockIdx.y * 64;
    int tx = t & 15, ty = t >> 4;
    float c[4][4] = {};
    for (int k0 = 0; k0 < 512; k0 += 16) {
        #pragma unroll
        for (int i = 0; i < 4; i++) {
            int id = t + i * 256;
            as_[id >> 4][id & 15] = g_y[(size_t)(m0 + (id >> 4)) * 512 + k0 + (id & 15)];
        }
        #pragma unroll
        for (int i = 0; i < 4; i++) {
            int id = t + i * 256;
            bs_[id >> 6][id & 63] = Wout[(size_t)(k0 + (id >> 6)) * 1024 + n0 + (id & 63)];
        }
        __syncthreads();
        #pragma unroll
        for (int kk = 0; kk < 16; kk++) {
            float ra[4], rb[4];
            #pragma unroll
            for (int i = 0; i < 4; i++) ra[i] = as_[ty + 16 * i][kk];
            #pragma unroll
            for (int j = 0; j < 4; j++) rb[j] = bs_[kk][tx + 16 * j];
            #pragma unroll
            for (int i = 0; i < 4; i++)
                #pragma unroll
                for (int j = 0; j < 4; j++) c[i][j] += ra[i] * rb[j];
        }
        __syncthreads();
    }
    #pragma unroll
    for (int i = 0; i < 4; i++)
        #pragma unroll
        for (int j = 0; j < 4; j++)
            out[(size_t)(m0 + ty + 16 * i) * 1024 + n0 + tx + 16 * j] = c[i][j];
}

// ------------------- launch -------------------
extern "C" void kernel_launch(void* const* d_in, const int* in_sizes, int n_in,
                              void* d_out, int out_size) {
    (void)in_sizes; (void)n_in; (void)out_size;
    const float* x   = (const float*)d_in[0];
    const float* lat = (const float*)d_in[1];
    const int*   mask = (const int*)d_in[2];          // bool -> int32 per harness contract
    const float* kvg = (const float*)d_in[3];
    const float* gm  = (const float*)d_in[4];
    const float* bm  = (const float*)d_in[5];
    const float* gl  = (const float*)d_in[6];
    const float* bl  = (const float*)d_in[7];
    const float* Wq  = (const float*)d_in[8];
    const float* Wk  = (const float*)d_in[9];
    const float* Wv  = (const float*)d_in[10];
    const float* Wout = (const float*)d_in[11];
    float* out = (float*)d_out;

    stats_x_kernel<<<ROWS_X, 128>>>(x);
    prep_t<<<dim3(16, 16), 256>>>(Wk, Wv, gm, bm);
    sum_parts<<<4, 256>>>();

    cudaFuncSetAttribute(gemm_kv, cudaFuncAttributeMaxDynamicSharedMemorySize, KV_SMEM);
    gemm_kv<<<dim3(8, 512), 256, KV_SMEM>>>();

    ln_lat_kernel<<<ROWS_L, 256>>>(lat, gl, bl);
    gemm_lat<<<dim3(24, 8), 256>>>(Wq, Wk, Wv, kvg);
    attn_kernel<<<dim3(SPLITS, H, Bb), 128>>>(mask);
    combine_kernel<<<512, 128>>>();
    gemm_out<<<dim3(16, 8), 256>>>(Wout, out);
}

// round 13
// speedup vs baseline: 3.8916x; 1.1247x over previous
#include <cuda_runtime.h>
#include <cuda_bf16.h>
#include <cstdint>
#include <cstddef>

#define DEV __device__ __forceinline__

namespace {
constexpr int Bb = 8, F = 8192, NL = 64, D = 1024, INNER = 512, H = 8, DH = 64;
constexpr int FN = F + NL;                 // 8256
constexpr int ROWS_X = Bb * F;             // 65536
constexpr int ROWS_L = Bb * NL;            // 512
constexpr int ROWS_KV = Bb * FN;           // 66048
constexpr float LN_EPS = 1e-5f;
constexpr float QSCALE = 0.125f;           // 64^-0.5
constexpr int SPLITS = 8;
constexpr int SPLEN = FN / SPLITS;         // 1032
constexpr int KV_SMEM = 3 * (4096 + 4096) * 4;   // 98304 B (3 stages x (A+B))
// attention smem (floats): ks[2][64*68] vs[2][64*68] ps[4][16*68] bias[2][64]
constexpr int AKS = 64 * 68;               // 4352 floats per stage
constexpr int ATTN_SMEM = (4 * AKS + 4 * 16 * 68 + 128) * 4;   // 87552 B
}

// ------------------- device scratch (static: no allocations allowed) -------------------
__device__ float g_mu[ROWS_X];
__device__ float g_rstd[ROWS_X];
__device__ float g_xr[(size_t)ROWS_X * D];        // tf32-rounded x
__device__ float g_latln[ROWS_L * D];
__device__ float g_bcatT[1024 * 1024];            // transposed gamma-folded [Wk|Wv]: [j][d], tf32-rounded
__device__ float g_partc[16 * 1024];
__device__ float g_partb[16 * 1024];
__device__ float g_csum[1024];
__device__ float g_bsum[1024];
__device__ float g_q[ROWS_L * INNER];             // tf32-rounded, pre-scaled
__device__ float g_k[(size_t)ROWS_KV * INNER];    // tf32-rounded
__device__ float g_v[(size_t)ROWS_KV * INNER];    // tf32-rounded
__device__ float g_y[ROWS_L * INNER];
__device__ float g_pm[Bb * H * SPLITS * NL];
__device__ float g_pl[Bb * H * SPLITS * NL];
__device__ float g_po[(size_t)Bb * H * SPLITS * NL * DH];

// ------------------- helpers -------------------
DEV unsigned f2tf(float x) {
    unsigned u;
    asm("cvt.rna.tf32.f32 %0, %1;" : "=r"(u) : "f"(x));
    return u;
}
DEV float rtf(float x) { return __uint_as_float(f2tf(x)); }

DEV unsigned smem_u32(const void* p) {
    unsigned a;
    asm("{ .reg .u64 t; cvta.to.shared.u64 t, %1; cvt.u32.u64 %0, t; }" : "=r"(a) : "l"(p));
    return a;
}

DEV void cpa16(unsigned dst, const float* src) {
    asm volatile("cp.async.cg.shared.global [%0], [%1], 16;\n" :: "r"(dst), "l"(src) : "memory");
}

DEV void mma_tf32(float c[4], const unsigned a[4], const unsigned b[2]) {
    asm volatile(
        "mma.sync.aligned.m16n8k8.row.col.f32.tf32.tf32.f32 "
        "{%0,%1,%2,%3},{%4,%5,%6,%7},{%8,%9},{%0,%1,%2,%3};\n"
        : "+f"(c[0]), "+f"(c[1]), "+f"(c[2]), "+f"(c[3])
        : "r"(a[0]), "r"(a[1]), "r"(a[2]), "r"(a[3]), "r"(b[0]), "r"(b[1]));
}

DEV void ldsm4(unsigned& r0, unsigned& r1, unsigned& r2, unsigned& r3, unsigned a) {
    asm volatile("ldmatrix.sync.aligned.m8n8.x4.shared.b16 {%0,%1,%2,%3}, [%4];"
                 : "=r"(r0), "=r"(r1), "=r"(r2), "=r"(r3) : "r"(a));
}

// ------------------- 1) per-row mean / rstd of x + tf32-rounded copy -------------------
__global__ void __launch_bounds__(128) stats_x_kernel(const float* __restrict__ x) {
    int r = blockIdx.x;
    const float4* xr = (const float4*)(x + (size_t)r * D);
    int t = threadIdx.x;
    float4 a = xr[t];
    float4 b = xr[t + 128];
    float s  = a.x + a.y + a.z + a.w + b.x + b.y + b.z + b.w;
    float ss = a.x * a.x + a.y * a.y + a.z * a.z + a.w * a.w
             + b.x * b.x + b.y * b.y + b.z * b.z + b.w * b.w;
    float4 ra, rb;
    ra.x = rtf(a.x); ra.y = rtf(a.y); ra.z = rtf(a.z); ra.w = rtf(a.w);
    rb.x = rtf(b.x); rb.y = rtf(b.y); rb.z = rtf(b.z); rb.w = rtf(b.w);
    float4* xw = (float4*)(g_xr + (size_t)r * D);
    xw[t] = ra;
    xw[t + 128] = rb;
    #pragma unroll
    for (int o = 16; o; o >>= 1) {
        s  += __shfl_xor_sync(0xffffffffu, s, o);
        ss += __shfl_xor_sync(0xffffffffu, ss, o);
    }
    __shared__ float sh[8];
    int w = t >> 5;
    if ((t & 31) == 0) { sh[w] = s; sh[w + 4] = ss; }
    __syncthreads();
    if (t == 0) {
        s  = sh[0] + sh[1] + sh[2] + sh[3];
        ss = sh[4] + sh[5] + sh[6] + sh[7];
        float mu = s * (1.f / D);
        float var = ss * (1.f / D) - mu * mu;
        g_mu[r] = mu;
        g_rstd[r] = rsqrtf(var + LN_EPS);
    }
}

// ------------------- 2) latent layernorm -------------------
__global__ void __launch_bounds__(256) ln_lat_kernel(const float* __restrict__ lat,
                                                     const float* __restrict__ gl,
                                                     const float* __restrict__ bl) {
    int r = blockIdx.x;
    int t = threadIdx.x;
    const float4* xr = (const float4*)(lat + (size_t)r * D);
    float4 a = xr[t];
    float s  = a.x + a.y + a.z + a.w;
    float ss = a.x * a.x + a.y * a.y + a.z * a.z + a.w * a.w;
    #pragma unroll
    for (int o = 16; o; o >>= 1) {
        s  += __shfl_xor_sync(0xffffffffu, s, o);
        ss += __shfl_xor_sync(0xffffffffu, ss, o);
    }
    __shared__ float sh[18];
    int w = t >> 5;
    if ((t & 31) == 0) { sh[w] = s; sh[8 + w] = ss; }
    __syncthreads();
    if (t == 0) {
        s = 0.f; ss = 0.f;
        #pragma unroll
        for (int i = 0; i < 8; i++) { s += sh[i]; ss += sh[8 + i]; }
        float mu = s * (1.f / D);
        float var = ss * (1.f / D) - mu * mu;
        sh[16] = mu;
        sh[17] = rsqrtf(var + LN_EPS);
    }
    __syncthreads();
    float mu = sh[16], rs = sh[17];
    float4 g4 = ((const float4*)gl)[t];
    float4 b4 = ((const float4*)bl)[t];
    float4 o;
    o.x = (a.x - mu) * rs * g4.x + b4.x;
    o.y = (a.y - mu) * rs * g4.y + b4.y;
    o.z = (a.z - mu) * rs * g4.z + b4.z;
    o.w = (a.w - mu) * rs * g4.w + b4.w;
    ((float4*)(g_latln + (size_t)r * D))[t] = o;
}

// ------------------- 3) prep: transpose + gamma-fold (tf32) + partial colsums -------------------
__global__ void __launch_bounds__(256) prep_t(const float* __restrict__ Wk,
                                              const float* __restrict__ Wv,
                                              const float* __restrict__ gm,
                                              const float* __restrict__ bm) {
    __shared__ float sg[64][65];
    __shared__ float redc[4][64];
    __shared__ float redb[4][64];
    int t = threadIdx.x;
    int j0 = blockIdx.x * 64, d0 = blockIdx.y * 64;
    int jc = t & 63;
    int j = j0 + jc;
    const float* W = (j < 512) ? Wk : Wv;
    int jl = (j < 512) ? j : (j - 512);
    float pc = 0.f, pb = 0.f;
    #pragma unroll
    for (int i = 0; i < 16; i++) {
        int dr = (t >> 6) + i * 4;
        int d = d0 + dr;
        float w = W[(size_t)d * 512 + jl];
        float gv = rtf(gm[d] * w);
        sg[dr][jc] = gv;
        pc += gv;
        pb += bm[d] * w;
    }
    redc[t >> 6][jc] = pc;
    redb[t >> 6][jc] = pb;
    __syncthreads();
    if (t < 64) {
        float c = redc[0][t] + redc[1][t] + redc[2][t] + redc[3][t];
        float b = redb[0][t] + redb[1][t] + redb[2][t] + redb[3][t];
        g_partc[blockIdx.y * 1024 + j0 + t] = c;
        g_partb[blockIdx.y * 1024 + j0 + t] = b;
    }
    #pragma unroll
    for (int i = 0; i < 16; i++) {
        int jr = (t >> 6) + i * 4;
        int dc = t & 63;
        g_bcatT[(size_t)(j0 + jr) * 1024 + d0 + dc] = sg[dc][jr];
    }
}

__global__ void __launch_bounds__(256) sum_parts() {
    int j = blockIdx.x * 256 + threadIdx.x;
    float c = 0.f, b = 0.f;
    #pragma unroll
    for (int i = 0; i < 16; i++) {
        c += g_partc[i * 1024 + j];
        b += g_partb[i * 1024 + j];
    }
    g_csum[j] = c;
    g_bsum[j] = b;
}

// ------------------- 4) big fused K/V GEMM: 3-stage cp.async + ldmatrix, 1 barrier/tile -------------------
DEV void kv_load_stage(unsigned sbase, int tid, int kt, int stage, int m0, int n0) {
    int k0 = kt * 32;
    unsigned abase = sbase + (unsigned)stage * 32768u;
    unsigned bbase = abase + 16384u;
    int row = tid >> 3;
    int atom = tid & 7;
    #pragma unroll
    for (int i = 0; i < 4; i++) {
        int r = row + i * 32;
        unsigned off = (unsigned)(r * 32 + ((atom ^ (r & 7)) << 2)) * 4u;
        cpa16(abase + off, g_xr + (size_t)(m0 + r) * 1024 + k0 + atom * 4);
        cpa16(bbase + off, g_bcatT + (size_t)(n0 + r) * 1024 + k0 + atom * 4);
    }
    asm volatile("cp.async.commit_group;\n" ::: "memory");
}

__global__ void __launch_bounds__(256) gemm_kv() {
    extern __shared__ unsigned sm[];
    unsigned sbase = smem_u32(sm);
    const int tid = threadIdx.x, warp = tid >> 5, lane = tid & 31;
    const int g = lane >> 2, tg = lane & 3;
    const int wm = warp >> 2, wn = warp & 3;
    const int m0 = blockIdx.y * 128, n0 = blockIdx.x * 128;

    const unsigned i7 = lane & 7;
    const unsigned mh = (lane >> 3) & 1;
    const unsigned ms = lane >> 4;
    const unsigned rowA = (unsigned)(wm * 64) + i7 + mh * 8;
    const unsigned rowB = (unsigned)(wn * 32) + ms * 8 + i7;

    float acc[4][4][4];
    #pragma unroll
    for (int a = 0; a < 4; a++)
        #pragma unroll
        for (int b = 0; b < 4; b++)
            #pragma unroll
            for (int c = 0; c < 4; c++) acc[a][b][c] = 0.f;

    kv_load_stage(sbase, tid, 0, 0, m0, n0);
    kv_load_stage(sbase, tid, 1, 1, m0, n0);

    int stage = 0;
    for (int kt = 0; kt < 32; kt++) {
        if (kt < 31) asm volatile("cp.async.wait_group 1;\n" ::: "memory");
        else         asm volatile("cp.async.wait_group 0;\n" ::: "memory");
        __syncthreads();

        if (kt < 30) {
            int ns = stage + 2; if (ns >= 3) ns -= 3;
            kv_load_stage(sbase, tid, kt + 2, ns, m0, n0);
        }

        const unsigned Ab = sbase + (unsigned)stage * 32768u;
        const unsigned Bbs = Ab + 16384u;
        #pragma unroll
        for (int ks = 0; ks < 4; ks++) {
            unsigned af[4][4], bf[4][2];
            const unsigned aAtom = (unsigned)(2 * ks) + ms;
            const unsigned bAtom = (unsigned)(2 * ks) + mh;
            #pragma unroll
            for (int mf = 0; mf < 4; mf++) {
                unsigned ad = Ab + ((rowA + mf * 16) * 32 + ((aAtom ^ i7) << 2)) * 4u;
                ldsm4(af[mf][0], af[mf][1], af[mf][2], af[mf][3], ad);
            }
            #pragma unroll
            for (int p = 0; p < 2; p++) {
                unsigned bd = Bbs + ((rowB + p * 16) * 32 + ((bAtom ^ i7) << 2)) * 4u;
                ldsm4(bf[2 * p][0], bf[2 * p][1], bf[2 * p + 1][0], bf[2 * p + 1][1], bd);
            }
            #pragma unroll
            for (int mf = 0; mf < 4; mf++)
                #pragma unroll
                for (int nf = 0; nf < 4; nf++)
                    mma_tf32(acc[mf][nf], af[mf], bf[nf]);
        }

        if (++stage >= 3) stage = 0;
    }

    // epilogue: fold layernorm, round to tf32, split K/V, remap rows
    #pragma unroll
    for (int mf = 0; mf < 4; mf++) {
        int r0 = m0 + wm * 64 + mf * 16 + g;
        int r1 = r0 + 8;
        float mu0 = g_mu[r0], rs0 = g_rstd[r0];
        float mu1 = g_mu[r1], rs1 = g_rstd[r1];
        size_t ro0 = (size_t)((r0 >> 13) * 8256 + (r0 & 8191));
        size_t ro1 = (size_t)((r1 >> 13) * 8256 + (r1 & 8191));
        #pragma unroll
        for (int nf = 0; nf < 4; nf++) {
            int c0 = n0 + wn * 32 + nf * 8 + 2 * tg;
            #pragma unroll
            for (int jj = 0; jj < 2; jj++) {
                int j = c0 + jj;
                float cs = g_csum[j], bs2 = g_bsum[j];
                float v0 = rtf(rs0 * (acc[mf][nf][jj] - mu0 * cs) + bs2);
                float v1 = rtf(rs1 * (acc[mf][nf][2 + jj] - mu1 * cs) + bs2);
                if (j < 512) {
                    g_k[ro0 * 512 + j] = v0;
                    g_k[ro1 * 512 + j] = v1;
                } else {
                    g_v[ro0 * 512 + (j - 512)] = v0;
                    g_v[ro1 * 512 + (j - 512)] = v1;
                }
            }
        }
    }
}

// ------------------- 5) latent Q/K/V GEMM (fp32 FFMA, small) -------------------
__global__ void __launch_bounds__(256) gemm_lat(const float* __restrict__ Wq,
                                                const float* __restrict__ Wk,
                                                const float* __restrict__ Wv,
                                                const float* __restrict__ kvg) {
    __shared__ float as_[64][17];
    __shared__ float bs_[16][65];
    int t = threadIdx.x;
    int n0 = blockIdx.x * 64, m0 = blockIdx.y * 64;
    int w = n0 >> 9;
    int nj0 = n0 & 511;
    const float* W = (w == 0) ? Wq : ((w == 1) ? Wk : Wv);
    int tx = t & 15, ty = t >> 4;
    float c[4][4] = {};
    for (int k0 = 0; k0 < 1024; k0 += 16) {
        #pragma unroll
        for (int i = 0; i < 4; i++) {
            int id = t + i * 256;
            as_[id >> 4][id & 15] = g_latln[(size_t)(m0 + (id >> 4)) * 1024 + k0 + (id & 15)];
        }
        #pragma unroll
        for (int i = 0; i < 4; i++) {
            int id = t + i * 256;
            bs_[id >> 6][id & 63] = W[(size_t)(k0 + (id >> 6)) * 512 + nj0 + (id & 63)];
        }
        __syncthreads();
        #pragma unroll
        for (int kk = 0; kk < 16; kk++) {
            float ra[4], rb[4];
            #pragma unroll
            for (int i = 0; i < 4; i++) ra[i] = as_[ty + 16 * i][kk];
            #pragma unroll
            for (int j = 0; j < 4; j++) rb[j] = bs_[kk][tx + 16 * j];
            #pragma unroll
            for (int i = 0; i < 4; i++)
                #pragma unroll
                for (int j = 0; j < 4; j++) c[i][j] += ra[i] * rb[j];
        }
        __syncthreads();
    }
    float gate = *kvg;
    #pragma unroll
    for (int i = 0; i < 4; i++)
        #pragma unroll
        for (int j = 0; j < 4; j++) {
            int m = m0 + ty + 16 * i;
            int J = n0 + tx + 16 * j;
            int b = m >> 6, li = m & 63;
            float v = c[i][j];
            if (w == 0) {
                g_q[(size_t)m * 512 + J] = rtf(v * QSCALE);
            } else if (w == 1) {
                g_k[((size_t)(b * 8256 + 8192 + li)) * 512 + (J - 512)] = rtf(v * gate);
            } else {
                g_v[((size_t)(b * 8256 + 8192 + li)) * 512 + (J - 1024)] = rtf(v * gate);
            }
        }
}

// ------------------- 6) split-KV flash attention: tf32 mma + cp.async double-buffer -------------------
DEV void attn_load_kv(unsigned ksb, unsigned vsb, int b, int h, int pos_base, int t) {
    #pragma unroll
    for (int i = 0; i < 8; i++) {
        int id = t + i * 128;
        int row = id >> 4, c4 = id & 15;
        int pos = pos_base + row;
        int grow = b * 8256 + (pos < 8255 ? pos : 8255);
        size_t go = (size_t)grow * 512 + h * 64 + c4 * 4;
        unsigned off = (unsigned)(row * 68 + c4 * 4) * 4u;
        cpa16(ksb + off, g_k + go);
        cpa16(vsb + off, g_v + go);
    }
    asm volatile("cp.async.commit_group;\n" ::: "memory");
}

__global__ void __launch_bounds__(128) attn_kernel(const int* __restrict__ mask) {
    extern __shared__ float smf[];
    unsigned sb = smem_u32(smf);

    const int s_ = blockIdx.x, h = blockIdx.y, b = blockIdx.z;
    const int t = threadIdx.x;
    const int wid = t >> 5, lane = t & 31;
    const int g = lane >> 2, tg = lane & 3;
    const int r0 = wid * 16;
    const int base = s_ * SPLEN;

    float* ksx[2] = { smf, smf + AKS };
    float* vsx[2] = { smf + 2 * AKS, smf + 3 * AKS };
    float* ps = smf + 4 * AKS + wid * (16 * 68);
    float* biasb = smf + 4 * AKS + 4 * 16 * 68;     // [2][64]
    unsigned ks_b[2] = { sb, sb + AKS * 4u };
    unsigned vs_b[2] = { sb + 2u * AKS * 4u, sb + 3u * AKS * 4u };

    // prologue: chunk 0 loads + bias
    attn_load_kv(ks_b[0], vs_b[0], b, h, base, t);
    if (t < 64) {
        int pos = base + t;
        bool valid = (pos < base + SPLEN) && (pos >= F || mask[b * F + pos] == 0);
        biasb[t] = valid ? 0.f : -1e30f;
    }

    // Q fragments (pre-rounded, pre-scaled in gmem)
    unsigned qf[8][4];
    {
        const float* q0 = g_q + (size_t)(b * 64 + r0 + g) * 512 + h * 64;
        const float* q1 = q0 + 8 * 512;
        #pragma unroll
        for (int kk = 0; kk < 8; kk++) {
            qf[kk][0] = __float_as_uint(q0[kk * 8 + tg]);
            qf[kk][1] = __float_as_uint(q1[kk * 8 + tg]);
            qf[kk][2] = __float_as_uint(q0[kk * 8 + tg + 4]);
            qf[kk][3] = __float_as_uint(q1[kk * 8 + tg + 4]);
        }
    }

    float m0 = -1e30f, m1 = -1e30f, l0 = 0.f, l1 = 0.f;
    float oacc[8][4];
    #pragma unroll
    for (int nf = 0; nf < 8; nf++)
        #pragma unroll
        for (int i = 0; i < 4; i++) oacc[nf][i] = 0.f;

    for (int kt = 0; kt < 17; kt++) {
        const int st = kt & 1;
        asm volatile("cp.async.wait_group 0;\n" ::: "memory");
        __syncthreads();    // chunk kt visible; all warps finished chunk kt-1

        if (kt < 16) {
            attn_load_kv(ks_b[st ^ 1], vs_b[st ^ 1], b, h, base + (kt + 1) * 64, t);
            if (t < 64) {
                int pos = base + (kt + 1) * 64 + t;
                bool valid = (pos < base + SPLEN) && (pos >= F || mask[b * F + pos] == 0);
                biasb[(st ^ 1) * 64 + t] = valid ? 0.f : -1e30f;
            }
        }

        const float* ks_ = ksx[st];
        const float* vs_ = vsx[st];
        const float* bi = biasb + st * 64;

        // S = Q @ K^T
        float sf[8][4];
        #pragma unroll
        for (int nf = 0; nf < 8; nf++)
            #pragma unroll
            for (int i = 0; i < 4; i++) sf[nf][i] = 0.f;
        #pragma unroll
        for (int kk = 0; kk < 8; kk++) {
            #pragma unroll
            for (int nf = 0; nf < 8; nf++) {
                unsigned bb[2];
                bb[0] = __float_as_uint(ks_[(nf * 8 + g) * 68 + kk * 8 + tg]);
                bb[1] = __float_as_uint(ks_[(nf * 8 + g) * 68 + kk * 8 + tg + 4]);
                mma_tf32(sf[nf], qf[kk], bb);
            }
        }

        // bias + online softmax
        float cm0 = -1e30f, cm1 = -1e30f;
        #pragma unroll
        for (int nf = 0; nf < 8; nf++) {
            float b0 = bi[nf * 8 + 2 * tg], b1 = bi[nf * 8 + 2 * tg + 1];
            sf[nf][0] += b0; sf[nf][1] += b1; sf[nf][2] += b0; sf[nf][3] += b1;
            cm0 = fmaxf(cm0, fmaxf(sf[nf][0], sf[nf][1]));
            cm1 = fmaxf(cm1, fmaxf(sf[nf][2], sf[nf][3]));
        }
        cm0 = fmaxf(cm0, __shfl_xor_sync(0xffffffffu, cm0, 1));
        cm0 = fmaxf(cm0, __shfl_xor_sync(0xffffffffu, cm0, 2));
        cm1 = fmaxf(cm1, __shfl_xor_sync(0xffffffffu, cm1, 1));
        cm1 = fmaxf(cm1, __shfl_xor_sync(0xffffffffu, cm1, 2));
        float mn0 = fmaxf(m0, cm0), mn1 = fmaxf(m1, cm1);
        float sc0 = __expf(m0 - mn0), sc1 = __expf(m1 - mn1);
        m0 = mn0; m1 = mn1;
        float rs0 = 0.f, rs1 = 0.f;
        #pragma unroll
        for (int nf = 0; nf < 8; nf++) {
            sf[nf][0] = __expf(sf[nf][0] - mn0);
            sf[nf][1] = __expf(sf[nf][1] - mn0);
            sf[nf][2] = __expf(sf[nf][2] - mn1);
            sf[nf][3] = __expf(sf[nf][3] - mn1);
            rs0 += sf[nf][0] + sf[nf][1];
            rs1 += sf[nf][2] + sf[nf][3];
        }
        rs0 += __shfl_xor_sync(0xffffffffu, rs0, 1);
        rs0 += __shfl_xor_sync(0xffffffffu, rs0, 2);
        rs1 += __shfl_xor_sync(0xffffffffu, rs1, 1);
        rs1 += __shfl_xor_sync(0xffffffffu, rs1, 2);
        l0 = l0 * sc0 + rs0;
        l1 = l1 * sc1 + rs1;
        #pragma unroll
        for (int nf = 0; nf < 8; nf++) {
            oacc[nf][0] *= sc0; oacc[nf][1] *= sc0;
            oacc[nf][2] *= sc1; oacc[nf][3] *= sc1;
        }

        // stage P (tf32) into warp-private buffer
        #pragma unroll
        for (int nf = 0; nf < 8; nf++) {
            float2 p0 = make_float2(rtf(sf[nf][0]), rtf(sf[nf][1]));
            float2 p1 = make_float2(rtf(sf[nf][2]), rtf(sf[nf][3]));
            *reinterpret_cast<float2*>(ps + g * 68 + nf * 8 + 2 * tg) = p0;
            *reinterpret_cast<float2*>(ps + (g + 8) * 68 + nf * 8 + 2 * tg) = p1;
        }
        __syncwarp();

        // O += P @ V
        #pragma unroll
        for (int kk = 0; kk < 8; kk++) {
            unsigned pa[4];
            pa[0] = __float_as_uint(ps[g * 68 + kk * 8 + tg]);
            pa[1] = __float_as_uint(ps[(g + 8) * 68 + kk * 8 + tg]);
            pa[2] = __float_as_uint(ps[g * 68 + kk * 8 + tg + 4]);
            pa[3] = __float_as_uint(ps[(g + 8) * 68 + kk * 8 + tg + 4]);
            #pragma unroll
            for (int nf = 0; nf < 8; nf++) {
                unsigned bb[2];
                bb[0] = __float_as_uint(vs_[(kk * 8 + tg) * 68 + nf * 8 + g]);
                bb[1] = __float_as_uint(vs_[(kk * 8 + tg + 4) * 68 + nf * 8 + g]);
                mma_tf32(oacc[nf], pa, bb);
            }
        }
        __syncwarp();
    }

    int idx0 = ((b * 8 + h) * 8 + s_) * 64 + r0 + g;
    int idx1 = idx0 + 8;
    if (tg == 0) {
        g_pm[idx0] = m0; g_pl[idx0] = l0;
        g_pm[idx1] = m1; g_pl[idx1] = l1;
    }
    #pragma unroll
    for (int nf = 0; nf < 8; nf++) {
        *reinterpret_cast<float2*>(g_po + (size_t)idx0 * 64 + nf * 8 + 2 * tg) =
            make_float2(oacc[nf][0], oacc[nf][1]);
        *reinterpret_cast<float2*>(g_po + (size_t)idx1 * 64 + nf * 8 + 2 * tg) =
            make_float2(oacc[nf][2], oacc[nf][3]);
    }
}

// ------------------- 7) split combine -> y -------------------
__global__ void __launch_bounds__(128) combine_kernel() {
    int bq = blockIdx.x;
    int b = bq >> 6, qr = bq & 63;
    int t = threadIdx.x;
    int h = t >> 4, c0 = (t & 15) * 4;
    int idx0 = ((b * 8 + h) * 8) * 64 + qr;
    float M = -1e30f;
    #pragma unroll
    for (int s = 0; s < SPLITS; s++) M = fmaxf(M, g_pm[idx0 + s * 64]);
    float L = 0.f;
    float a[4] = {0.f, 0.f, 0.f, 0.f};
    #pragma unroll
    for (int s = 0; s < SPLITS; s++) {
        float w = __expf(g_pm[idx0 + s * 64] - M);
        L += g_pl[idx0 + s * 64] * w;
        size_t pb = (size_t)(idx0 + s * 64) * 64 + c0;
        #pragma unroll
        for (int j = 0; j < 4; j++) a[j] += g_po[pb + j] * w;
    }
    float inv = 1.f / L;
    size_t yo = (size_t)(b * 64 + qr) * 512 + h * 64 + c0;
    #pragma unroll
    for (int j = 0; j < 4; j++) g_y[yo + j] = a[j] * inv;
}

// ------------------- 8) output projection: out = y @ Wout -------------------
__global__ void __launch_bounds__(256) gemm_out(const float* __restrict__ Wout,
                                                float* __restrict__ out) {
    __shared__ float as_[64][17];
    __shared__ float bs_[16][65];
    int t = threadIdx.x;
    int n0 = blockIdx.x * 64, m0 = blockIdx.y * 64;
    int tx = t & 15, ty = t >> 4;
    float c[4][4] = {};
    for (int k0 = 0; k0 < 512; k0 += 16) {
        #pragma unroll
        for (int i = 0; i < 4; i++) {
            int id = t + i * 256;
            as_[id >> 4][id & 15] = g_y[(size_t)(m0 + (id >> 4)) * 512 + k0 + (id & 15)];
        }
        #pragma unroll
        for (int i = 0; i < 4; i++) {
            int id = t + i * 256;
            bs_[id >> 6][id & 63] = Wout[(size_t)(k0 + (id >> 6)) * 1024 + n0 + (id & 63)];
        }
        __syncthreads();
        #pragma unroll
        for (int kk = 0; kk < 16; kk++) {
            float ra[4], rb[4];
            #pragma unroll
            for (int i = 0; i < 4; i++) ra[i] = as_[ty + 16 * i][kk];
            #pragma unroll
            for (int j = 0; j < 4; j++) rb[j] = bs_[kk][tx + 16 * j];
            #pragma unroll
            for (int i = 0; i < 4; i++)
                #pragma unroll
                for (int j = 0; j < 4; j++) c[i][j] += ra[i] * rb[j];
        }
        __syncthreads();
    }
    #pragma unroll
    for (int i = 0; i < 4; i++)
        #pragma unroll
        for (int j = 0; j < 4; j++)
            out[(size_t)(m0 + ty + 16 * i) * 1024 + n0 + tx + 16 * j] = c[i][j];
}

// ------------------- launch -------------------
extern "C" void kernel_launch(void* const* d_in, const int* in_sizes, int n_in,
                              void* d_out, int out_size) {
    (void)in_sizes; (void)n_in; (void)out_size;
    const float* x   = (const float*)d_in[0];
    const float* lat = (const float*)d_in[1];
    const int*   mask = (const int*)d_in[2];          // bool -> int32 per harness contract
    const float* kvg = (const float*)d_in[3];
    const float* gm  = (const float*)d_in[4];
    const float* bm  = (const float*)d_in[5];
    const float* gl  = (const float*)d_in[6];
    const float* bl  = (const float*)d_in[7];
    const float* Wq  = (const float*)d_in[8];
    const float* Wk  = (const float*)d_in[9];
    const float* Wv  = (const float*)d_in[10];
    const float* Wout = (const float*)d_in[11];
    float* out = (float*)d_out;

    stats_x_kernel<<<ROWS_X, 128>>>(x);
    prep_t<<<dim3(16, 16), 256>>>(Wk, Wv, gm, bm);
    sum_parts<<<4, 256>>>();

    cudaFuncSetAttribute(gemm_kv, cudaFuncAttributeMaxDynamicSharedMemorySize, KV_SMEM);
    gemm_kv<<<dim3(8, 512), 256, KV_SMEM>>>();

    ln_lat_kernel<<<ROWS_L, 256>>>(lat, gl, bl);
    gemm_lat<<<dim3(24, 8), 256>>>(Wq, Wk, Wv, kvg);

    cudaFuncSetAttribute(attn_kernel, cudaFuncAttributeMaxDynamicSharedMemorySize, ATTN_SMEM);
    attn_kernel<<<dim3(SPLITS, H, Bb), 128, ATTN_SMEM>>>(mask);

    combine_kernel<<<512, 128>>>();
    gemm_out<<<dim3(16, 8), 256>>>(Wout, out);
}